// round 9
// baseline (speedup 1.0000x reference)
#include <cuda_runtime.h>
#include <cuda_fp16.h>
#include <math.h>
#include <stdint.h>

// ===========================================================================
// AttentionBlock B=8,S=2048,D=512 — mma.sync fp16, precision-tiered GEMMs
// R9: BK=64 (half the barriers), generalized ld strides, direct v^T GEMM.
// ===========================================================================

#define MTOT (16384 * 512)
__device__ __half g_xh[MTOT];
__device__ __half g_qh[MTOT];
__device__ __half g_kh[MTOT];
__device__ __half g_vth[MTOT];                      // v^T [512][16384] fp16
__device__ __half g_onh[MTOT], g_onl[MTOT];
__device__ __half g_hh[MTOT],  g_hl[MTOT];          // h1
__device__ __half g_h2h[MTOT], g_h2l[MTOT];         // h2
__device__ __half g_sh[8LL * 2048 * 2048];
__device__ __half g_wth[6 * 512 * 512];             // W^T [N][K], fp16
__device__ float g_t [MTOT];
__device__ float g_on[MTOT];

// ---------------- helpers ----------------
__device__ __forceinline__ uint32_t smem_u32(const void* p) {
    uint32_t a;
    asm("{ .reg .u64 t; cvta.to.shared.u64 t, %1; cvt.u32.u64 %0, t; }"
        : "=r"(a) : "l"(p));
    return a;
}
__device__ __forceinline__ void cpa16(uint32_t dst, const void* src) {
    asm volatile("cp.async.cg.shared.global [%0], [%1], 16;"
                 :: "r"(dst), "l"(src) : "memory");
}
#define CP_COMMIT() asm volatile("cp.async.commit_group;" ::: "memory")
#define CP_WAIT0()  asm volatile("cp.async.wait_group 0;"  ::: "memory")
#define CP_WAIT1()  asm volatile("cp.async.wait_group 1;"  ::: "memory")

#define MMA_F16(c, a0, a1, a2, a3, b0, b1)                                    \
    asm volatile("mma.sync.aligned.m16n8k16.row.col.f32.f16.f16.f32 "         \
        "{%0,%1,%2,%3}, {%4,%5,%6,%7}, {%8,%9}, {%0,%1,%2,%3};"               \
        : "+f"((c)[0]), "+f"((c)[1]), "+f"((c)[2]), "+f"((c)[3])              \
        : "r"(a0), "r"(a1), "r"(a2), "r"(a3), "r"(b0), "r"(b1))

__device__ __forceinline__ void ldsm_x4(uint32_t& r0, uint32_t& r1,
                                        uint32_t& r2, uint32_t& r3, uint32_t a) {
    asm volatile("ldmatrix.sync.aligned.m8n8.x4.shared.b16 {%0,%1,%2,%3}, [%4];"
                 : "=r"(r0), "=r"(r1), "=r"(r2), "=r"(r3) : "r"(a));
}

__device__ __forceinline__ void split2(float a, float b, __half2& h, __half2& l) {
    h = __floats2half2_rn(a, b);
    l = __floats2half2_rn(a - __half2float(h.x), b - __half2float(h.y));
}

// ---------------- GEMM ----------------
// Block tile 128x128, BK=64, 8 warps (2x4), warp tile 64x32.
// Row stride in smem: 128B data + 16B pad = 144B (conflict-free).
// NPROD=1: planes [A,B],      3-stage
// NPROD=2: planes [Ah,Al,Bh], 2-stage
// OUTM: 0 = fp32 C; 1 = split hi+lo; 2 = hi only.
// biasMode: 0 = bias[col], 1 = bias[row].
#define RSTRIDE 144
#define PLANE_B (128 * RSTRIDE)     // 18432
#define SMEM_P1 (3 * 2 * PLANE_B)   // 110592
#define SMEM_P2 (2 * 3 * PLANE_B)   // 110592

template <int NPROD, int OUTM>
__global__ __launch_bounds__(256, 2) void mma_gemm(
    const __half* __restrict__ Ah, const __half* __restrict__ Al,
    const __half* __restrict__ Bh,
    const float* __restrict__ bias, int biasMode,
    float* __restrict__ Cf, __half* __restrict__ Ch, __half* __restrict__ Cl,
    int ldA, int ldB, int ldC, int K, float alpha,
    long long sA, long long sB, long long sC)
{
    constexpr int NPLANES = (NPROD == 1) ? 2 : 3;
    constexpr int NSTG    = (NPROD == 1) ? 3 : 2;
    constexpr uint32_t STAGE = NPLANES * PLANE_B;
    constexpr uint32_t BOFF  = (NPROD == 1) ? PLANE_B : 2 * PLANE_B;

    extern __shared__ __align__(16) uint32_t sm[];
    const uint32_t sbase = smem_u32(sm);

    const int bz = blockIdx.z;
    Ah += (long long)bz * sA;
    if (NPROD >= 2) Al += (long long)bz * sA;
    Bh += (long long)bz * sB;

    const int m0 = blockIdx.y * 128;
    const int n0 = blockIdx.x * 128;
    const int tid  = threadIdx.x;
    const int wid  = tid >> 5, lane = tid & 31;
    const int wm   = wid >> 2, wn = wid & 3;      // warp tile 64 x 32
    const int g    = lane >> 2, t = lane & 3;

    // loader: 2 threads per row, 64B (4 x 16B) each, per plane
    const int lrow = tid >> 1;
    const int lhalf = (tid & 1);
    const char* gAh = (const char*)(Ah + (long long)(m0 + lrow) * ldA) + lhalf * 64;
    const char* gAl = (NPROD >= 2)
        ? (const char*)(Al + (long long)(m0 + lrow) * ldA) + lhalf * 64 : nullptr;
    const char* gBh = (const char*)(Bh + (long long)(n0 + lrow) * ldB) + lhalf * 64;
    const uint32_t dst0 = sbase + lrow * RSTRIDE + lhalf * 64;

    // ldmatrix per-lane base offsets (within a plane)
    const uint32_t a_off = (uint32_t)(wm * 64 + (lane & 15)) * RSTRIDE
                         + (uint32_t)(lane >> 4) * 16u;
    const uint32_t b_off = (uint32_t)(wn * 32 + (lane & 7) + ((lane >> 4) & 1) * 8) * RSTRIDE
                         + (uint32_t)((lane >> 3) & 1) * 16u;

    float acc[4][4][4];
#pragma unroll
    for (int i = 0; i < 4; i++)
#pragma unroll
        for (int j = 0; j < 4; j++)
#pragma unroll
            for (int e = 0; e < 4; e++) acc[i][j][e] = 0.0f;

    const int NCH = K >> 6;   // BK = 64

    auto PREF = [&](int chv) {
        const uint32_t so = (uint32_t)(chv % NSTG) * STAGE;
        const long long go = (long long)chv * 128;      // 64 halves = 128 bytes
#pragma unroll
        for (int s = 0; s < 4; s++)
            cpa16(dst0 + so + s * 16, gAh + go + s * 16);
        if (NPROD >= 2) {
#pragma unroll
            for (int s = 0; s < 4; s++)
                cpa16(dst0 + so + PLANE_B + s * 16, gAl + go + s * 16);
        }
#pragma unroll
        for (int s = 0; s < 4; s++)
            cpa16(dst0 + so + BOFF + s * 16, gBh + go + s * 16);
    };

    auto COMPUTE = [&](int ch) {
        const uint32_t sb = sbase + (uint32_t)(ch % NSTG) * STAGE;
        const uint32_t aA = sb + a_off;
        const uint32_t aB = sb + BOFF + b_off;
        const uint32_t aAl2 = sb + PLANE_B + a_off;
#pragma unroll
        for (int ks = 0; ks < 4; ks++) {
            const uint32_t ko = ks * 32;
            uint32_t bh[4][2];
            ldsm_x4(bh[0][0], bh[0][1], bh[1][0], bh[1][1], aB + ko);
            ldsm_x4(bh[2][0], bh[2][1], bh[3][0], bh[3][1], aB + 16 * RSTRIDE + ko);
#pragma unroll
            for (int mi = 0; mi < 4; mi++) {
                uint32_t ah[4];
                ldsm_x4(ah[0], ah[1], ah[2], ah[3], aA + mi * 16 * RSTRIDE + ko);
#pragma unroll
                for (int ni = 0; ni < 4; ni++)
                    MMA_F16(acc[mi][ni], ah[0], ah[1], ah[2], ah[3], bh[ni][0], bh[ni][1]);
                if (NPROD >= 2) {
                    uint32_t al[4];
                    ldsm_x4(al[0], al[1], al[2], al[3], aAl2 + mi * 16 * RSTRIDE + ko);
#pragma unroll
                    for (int ni = 0; ni < 4; ni++)
                        MMA_F16(acc[mi][ni], al[0], al[1], al[2], al[3], bh[ni][0], bh[ni][1]);
                }
            }
        }
    };

    // pipeline: NSTG stages, 1 sync per chunk
    {
        const int npre = (NCH < NSTG - 1) ? NCH : (NSTG - 1);
        for (int i = 0; i < npre; i++) { PREF(i); CP_COMMIT(); }
    }
    for (int ch = 0; ch < NCH; ch++) {
        int w = NSTG - 2;
        const int rem = NCH - 1 - ch;
        if (rem < w) w = rem;
        if (w <= 0)      CP_WAIT0();
        else             CP_WAIT1();
        __syncthreads();
        if (ch + NSTG - 1 < NCH) { PREF(ch + NSTG - 1); CP_COMMIT(); }
        COMPUTE(ch);
    }

    // ---------------- epilogue ----------------
    float*  CfB = Cf + (long long)bz * sC;
    __half* ChB = Ch + (long long)bz * sC;
    __half* ClB = Cl + (long long)bz * sC;

#pragma unroll
    for (int mi = 0; mi < 4; mi++) {
#pragma unroll
        for (int ni = 0; ni < 4; ni++) {
            const int r0 = m0 + wm * 64 + mi * 16 + g;
            const int c  = n0 + wn * 32 + ni * 8 + t * 2;
            float v0 = acc[mi][ni][0] * alpha, v1 = acc[mi][ni][1] * alpha;
            float v2 = acc[mi][ni][2] * alpha, v3 = acc[mi][ni][3] * alpha;
            if (bias) {
                if (biasMode == 0) {
                    const float b0 = bias[c], b1 = bias[c + 1];
                    v0 += b0; v1 += b1; v2 += b0; v3 += b1;
                } else {
                    const float br0 = bias[r0], br8 = bias[r0 + 8];
                    v0 += br0; v1 += br0; v2 += br8; v3 += br8;
                }
            }
            if (OUTM == 0) {
                *(float2*)&CfB[(long long)r0 * ldC + c]       = make_float2(v0, v1);
                *(float2*)&CfB[(long long)(r0 + 8) * ldC + c] = make_float2(v2, v3);
            } else if (OUTM == 1) {
                __half2 h0, l0, h1, l1;
                split2(v0, v1, h0, l0);
                split2(v2, v3, h1, l1);
                ((__half2*)ChB)[((long long)r0 * ldC + c) >> 1]       = h0;
                ((__half2*)ClB)[((long long)r0 * ldC + c) >> 1]       = l0;
                ((__half2*)ChB)[((long long)(r0 + 8) * ldC + c) >> 1] = h1;
                ((__half2*)ClB)[((long long)(r0 + 8) * ldC + c) >> 1] = l1;
            } else {
                ((__half2*)ChB)[((long long)r0 * ldC + c) >> 1]       = __floats2half2_rn(v0, v1);
                ((__half2*)ChB)[((long long)(r0 + 8) * ldC + c) >> 1] = __floats2half2_rn(v2, v3);
            }
        }
    }
}

// ---------------- fp32 -> fp16 ----------------
__global__ __launch_bounds__(256) void tohalf_kernel(
    const float* __restrict__ in, __half* __restrict__ oh, int n4)
{
    const int i = blockIdx.x * 256 + threadIdx.x;
    if (i >= n4) return;
    float4 v = ((const float4*)in)[i];
    ((__half2*)oh)[i * 2]     = __floats2half2_rn(v.x, v.y);
    ((__half2*)oh)[i * 2 + 1] = __floats2half2_rn(v.z, v.w);
}

// ------------- transpose: fp32 [R][C] -> fp16 [C][R] ----------
__global__ __launch_bounds__(256) void tsplit_kernel(
    const float* __restrict__ in, __half* __restrict__ oh,
    int R, int C, long long sI, long long sO)
{
    __shared__ float tile[32][33];
    const int z = blockIdx.z;
    in += (long long)z * sI;
    oh += (long long)z * sO;
    const int c0 = blockIdx.x * 32, r0 = blockIdx.y * 32;
    const int tx = threadIdx.x & 31, ty = threadIdx.x >> 5;

#pragma unroll
    for (int i = 0; i < 4; i++)
        tile[ty + i * 8][tx] = in[(long long)(r0 + ty + i * 8) * C + c0 + tx];
    __syncthreads();
#pragma unroll
    for (int i = 0; i < 4; i++) {
        const float v = tile[tx][ty + i * 8];
        oh[(long long)(c0 + ty + i * 8) * R + r0 + tx] = __float2half_rn(v);
    }
}

// -------- softmax, in-place on fp16 plane (row = 2048) --------
__device__ __forceinline__ float warpMax(float v) {
#pragma unroll
    for (int o = 16; o > 0; o >>= 1) v = fmaxf(v, __shfl_xor_sync(0xffffffffu, v, o));
    return v;
}
__device__ __forceinline__ float warpSum(float v) {
#pragma unroll
    for (int o = 16; o > 0; o >>= 1) v += __shfl_xor_sync(0xffffffffu, v, o);
    return v;
}

__global__ __launch_bounds__(256) void softmax_kernel(__half* __restrict__ H)
{
    const long long base = (long long)blockIdx.x * 2048;
    __half2* rh = (__half2*)(H + base);
    const int tid = threadIdx.x;
    const int lane = tid & 31, wid = tid >> 5;
    __shared__ float sh[8];

    float v[8];
#pragma unroll
    for (int j = 0; j < 4; j++) {
        const __half2 hv = rh[tid * 4 + j];
        v[2*j]   = __half2float(hv.x);
        v[2*j+1] = __half2float(hv.y);
    }

    float m = v[0];
#pragma unroll
    for (int i = 1; i < 8; i++) m = fmaxf(m, v[i]);
    m = warpMax(m);
    if (lane == 0) sh[wid] = m;
    __syncthreads();
    m = sh[0];
#pragma unroll
    for (int w = 1; w < 8; w++) m = fmaxf(m, sh[w]);

    float e[8];
    float s = 0.0f;
#pragma unroll
    for (int i = 0; i < 8; i++) { e[i] = __expf(v[i] - m); s += e[i]; }
    s = warpSum(s);
    __syncthreads();
    if (lane == 0) sh[wid] = s;
    __syncthreads();
    float tot = 0.0f;
#pragma unroll
    for (int w = 0; w < 8; w++) tot += sh[w];
    const float inv = 1.0f / tot;

#pragma unroll
    for (int j = 0; j < 4; j++)
        rh[tid * 4 + j] = __floats2half2_rn(e[2*j] * inv, e[2*j+1] * inv);
}

// ---------------- fused add(+gelu)+LN ----------------
template <int MODE, bool WF32>
__global__ __launch_bounds__(128) void rowln_kernel(
    const float* __restrict__ X, const float* __restrict__ Y,
    const float* __restrict__ g, const float* __restrict__ b,
    float* __restrict__ Of, __half* __restrict__ Oh, __half* __restrict__ Ol)
{
    const long long row = (long long)blockIdx.x * 512;
    const int tid = threadIdx.x;
    const int lane = tid & 31, wid = tid >> 5;
    __shared__ float s1[4], s2[4];

    float t[4];
    float sum = 0.0f, sq = 0.0f;
#pragma unroll
    for (int i = 0; i < 4; i++) {
        const int c = tid + i * 128;
        float u = X[row + c] + Y[row + c];
        if (MODE == 1) u = 0.5f * u * (1.0f + erff(u * 0.7071067811865476f));
        t[i] = u;
        sum += u;
        sq += u * u;
    }
    sum = warpSum(sum);
    sq = warpSum(sq);
    if (lane == 0) { s1[wid] = sum; s2[wid] = sq; }
    __syncthreads();
    float ts = 0.0f, tq = 0.0f;
#pragma unroll
    for (int w = 0; w < 4; w++) { ts += s1[w]; tq += s2[w]; }
    const float mean = ts * (1.0f / 512.0f);
    const float var = tq * (1.0f / 512.0f) - mean * mean;
    const float inv = rsqrtf(var + 1e-5f);

#pragma unroll
    for (int i = 0; i < 4; i++) {
        const int c = tid + i * 128;
        const float o = (t[i] - mean) * inv * g[c] + b[c];
        if (WF32) Of[row + c] = o;
        const __half h = __float2half_rn(o);
        Oh[row + c] = h;
        Ol[row + c] = __float2half_rn(o - __half2float(h));
    }
}

// ---------------- host ----------------
template <typename T>
static T* symaddr(const void* sym)
{
    void* p = nullptr;
    cudaGetSymbolAddress(&p, sym);
    return (T*)p;
}

extern "C" void kernel_launch(void* const* d_in, const int* in_sizes, int n_in,
                              void* d_out, int out_size)
{
    const float* x    = (const float*)d_in[0];
    const float* Wq   = (const float*)d_in[1];
    const float* bq   = (const float*)d_in[2];
    const float* Wk   = (const float*)d_in[3];
    const float* bk   = (const float*)d_in[4];
    const float* Wv   = (const float*)d_in[5];
    const float* bv   = (const float*)d_in[6];
    const float* ln0g = (const float*)d_in[7];
    const float* ln0b = (const float*)d_in[8];
    const float* W1   = (const float*)d_in[9];
    const float* b1   = (const float*)d_in[10];
    const float* ln1g = (const float*)d_in[11];
    const float* ln1b = (const float*)d_in[12];
    const float* W2   = (const float*)d_in[13];
    const float* b2   = (const float*)d_in[14];
    const float* ln2g = (const float*)d_in[15];
    const float* ln2b = (const float*)d_in[16];
    const float* W3   = (const float*)d_in[17];
    const float* b3   = (const float*)d_in[18];
    float* out = (float*)d_out;

    __half* xh  = symaddr<__half>(g_xh);
    __half* qh  = symaddr<__half>(g_qh);
    __half* kh  = symaddr<__half>(g_kh);
    __half* vth = symaddr<__half>(g_vth);
    __half* onh = symaddr<__half>(g_onh);  __half* onl = symaddr<__half>(g_onl);
    __half* hh  = symaddr<__half>(g_hh);   __half* hl  = symaddr<__half>(g_hl);
    __half* h2h = symaddr<__half>(g_h2h);  __half* h2l = symaddr<__half>(g_h2l);
    __half* sh_ = symaddr<__half>(g_sh);
    __half* wth = symaddr<__half>(g_wth);
    float* tt = symaddr<float>(g_t);
    float* on = symaddr<float>(g_on);

    cudaFuncSetAttribute(mma_gemm<1,0>, cudaFuncAttributeMaxDynamicSharedMemorySize, SMEM_P1);
    cudaFuncSetAttribute(mma_gemm<1,2>, cudaFuncAttributeMaxDynamicSharedMemorySize, SMEM_P1);
    cudaFuncSetAttribute(mma_gemm<2,0>, cudaFuncAttributeMaxDynamicSharedMemorySize, SMEM_P2);

    const long long sSD = 2048LL * 512;
    const long long sSS = 2048LL * 2048;
    const long long WSZ = 512LL * 512;
    const float scale = 0.044194173824159216f;   // 1/sqrt(512)

    dim3 gW(16, 16, 1);
    dim3 bT(256);
    dim3 gProj(4, 128, 1);     // N=512, M=16384
    dim3 gScores(16, 16, 8);   // per batch 2048x2048
    dim3 gVt(128, 4, 1);       // M=512, N=16384
    dim3 gAtt(4, 16, 8);

    // 1-3: q/k path inputs
    tohalf_kernel<<<MTOT / 1024, 256>>>(x, xh, MTOT / 4);
    tsplit_kernel<<<gW, bT>>>(Wq, wth + 0 * WSZ, 512, 512, 0, 0);
    tsplit_kernel<<<gW, bT>>>(Wk, wth + 1 * WSZ, 512, 512, 0, 0);

    // 4-5: q, k (fp16 out, NPROD=1)
    mma_gemm<1,2><<<gProj, 256, SMEM_P1>>>(xh, nullptr, wth + 0 * WSZ,
        bq, 0, nullptr, qh, nullptr, 512, 512, 512, 512, 1.0f, 0, 0, 0);
    mma_gemm<1,2><<<gProj, 256, SMEM_P1>>>(xh, nullptr, wth + 1 * WSZ,
        bk, 0, nullptr, kh, nullptr, 512, 512, 512, 512, 1.0f, 0, 0, 0);

    // 6: scores = q @ k^T * scale (ncu profiles this launch)
    mma_gemm<1,2><<<gScores, 256, SMEM_P1>>>(qh, nullptr, kh,
        nullptr, 0, nullptr, sh_, nullptr, 512, 512, 2048, 512, scale, sSD, sSD, sSS);

    // 7: softmax in-place
    softmax_kernel<<<16384, 256>>>(sh_);

    // 8-9: v^T = Wv^T @ x^T directly (row bias bv), fp16 out [512][16384]
    tsplit_kernel<<<gW, bT>>>(Wv, wth + 2 * WSZ, 512, 512, 0, 0);
    mma_gemm<1,2><<<gVt, 256, SMEM_P1>>>(wth + 2 * WSZ, nullptr, xh,
        bv, 1, nullptr, vth, nullptr, 512, 512, 16384, 512, 1.0f, 0, 0, 0);

    // 10: att = w @ v  (B = v^T rows, ldB=16384, per-batch col offset 2048)
    mma_gemm<1,0><<<gAtt, 256, SMEM_P1>>>(sh_, nullptr, vth,
        nullptr, 0, tt, nullptr, nullptr, 2048, 16384, 512, 2048, 1.0f, sSS, 2048, sSD);

    // 11: out_nxt = LN(x + att)
    rowln_kernel<0, true><<<16384, 128>>>(x, tt, ln0g, ln0b, on, onh, onl);

    // 12-14: h1 (NPROD=2: A split, W rounded)
    tsplit_kernel<<<gW, bT>>>(W1, wth + 3 * WSZ, 512, 512, 0, 0);
    mma_gemm<2,0><<<gProj, 256, SMEM_P2>>>(onh, onl, wth + 3 * WSZ,
        b1, 0, tt, nullptr, nullptr, 512, 512, 512, 512, 1.0f, 0, 0, 0);
    rowln_kernel<1, false><<<16384, 128>>>(on, tt, ln1g, ln1b, nullptr, hh, hl);

    // 15-17: h2 (NPROD=2)
    tsplit_kernel<<<gW, bT>>>(W2, wth + 4 * WSZ, 512, 512, 0, 0);
    mma_gemm<2,0><<<gProj, 256, SMEM_P2>>>(hh, hl, wth + 4 * WSZ,
        b2, 0, tt, nullptr, nullptr, 512, 512, 512, 512, 1.0f, 0, 0, 0);
    rowln_kernel<1, false><<<16384, 128>>>(on, tt, ln2g, ln2b, nullptr, h2h, h2l);

    // 18-19: out = h2 @ W3 + b3 (NPROD=2)
    tsplit_kernel<<<gW, bT>>>(W3, wth + 5 * WSZ, 512, 512, 0, 0);
    mma_gemm<2,0><<<gProj, 256, SMEM_P2>>>(h2h, h2l, wth + 5 * WSZ,
        b3, 0, out, nullptr, nullptr, 512, 512, 512, 512, 1.0f, 0, 0, 0);
}

// round 10
// speedup vs baseline: 1.0311x; 1.0311x over previous
#include <cuda_runtime.h>
#include <cuda_fp16.h>
#include <math.h>
#include <stdint.h>

// ===========================================================================
// AttentionBlock B=8,S=2048,D=512 — mma.sync fp16, precision-tiered GEMMs
// R10: 256x128 block tile / 512 threads / 16 warps (crossbar-traffic cut),
//      BK=32 revert, fused q+k GEMM, direct v^T GEMM.
// ===========================================================================

#define MTOT (16384 * 512)
__device__ __half g_xh[MTOT];
__device__ __half g_qkh[16384 * 1024];              // q|k fused [16384][1024]
__device__ __half g_vth[MTOT];                      // v^T [512][16384] fp16
__device__ __half g_onh[MTOT], g_onl[MTOT];
__device__ __half g_hh[MTOT],  g_hl[MTOT];          // h1
__device__ __half g_h2h[MTOT], g_h2l[MTOT];         // h2
__device__ __half g_sh[8LL * 2048 * 2048];
__device__ __half g_wth[6 * 512 * 512];             // W^T planes
__device__ float g_bqk[1024];
__device__ float g_t [MTOT];
__device__ float g_on[MTOT];

// ---------------- helpers ----------------
__device__ __forceinline__ uint32_t smem_u32(const void* p) {
    uint32_t a;
    asm("{ .reg .u64 t; cvta.to.shared.u64 t, %1; cvt.u32.u64 %0, t; }"
        : "=r"(a) : "l"(p));
    return a;
}
__device__ __forceinline__ void cpa16(uint32_t dst, const void* src) {
    asm volatile("cp.async.cg.shared.global [%0], [%1], 16;"
                 :: "r"(dst), "l"(src) : "memory");
}
#define CP_COMMIT() asm volatile("cp.async.commit_group;" ::: "memory")
#define CP_WAIT0()  asm volatile("cp.async.wait_group 0;"  ::: "memory")
#define CP_WAIT1()  asm volatile("cp.async.wait_group 1;"  ::: "memory")
#define CP_WAIT2()  asm volatile("cp.async.wait_group 2;"  ::: "memory")

#define MMA_F16(c, a0, a1, a2, a3, b0, b1)                                    \
    asm volatile("mma.sync.aligned.m16n8k16.row.col.f32.f16.f16.f32 "         \
        "{%0,%1,%2,%3}, {%4,%5,%6,%7}, {%8,%9}, {%0,%1,%2,%3};"               \
        : "+f"((c)[0]), "+f"((c)[1]), "+f"((c)[2]), "+f"((c)[3])              \
        : "r"(a0), "r"(a1), "r"(a2), "r"(a3), "r"(b0), "r"(b1))

__device__ __forceinline__ void ldsm_x4(uint32_t& r0, uint32_t& r1,
                                        uint32_t& r2, uint32_t& r3, uint32_t a) {
    asm volatile("ldmatrix.sync.aligned.m8n8.x4.shared.b16 {%0,%1,%2,%3}, [%4];"
                 : "=r"(r0), "=r"(r1), "=r"(r2), "=r"(r3) : "r"(a));
}

__device__ __forceinline__ void split2(float a, float b, __half2& h, __half2& l) {
    h = __floats2half2_rn(a, b);
    l = __floats2half2_rn(a - __half2float(h.x), b - __half2float(h.y));
}

// ---------------- GEMM ----------------
// Block tile 256(M) x 128(N), BK=32, 512 threads, 16 warps (4x4),
// warp tile 64x32. Smem row: 64B data + 16B pad = 80B.
// NPROD=1: planes [A,B],      4-stage
// NPROD=2: planes [Ah,Al,Bh], 3-stage
// OUTM: 0 = fp32 C; 1 = split hi+lo; 2 = hi only.  biasMode: 0=col, 1=row.
#define RSTRIDE 80
#define APLANE (256 * RSTRIDE)      // 20480
#define BPLANE (128 * RSTRIDE)      // 10240
#define SMEM_P1 (4 * (APLANE + BPLANE))        // 122880
#define SMEM_P2 (3 * (2 * APLANE + BPLANE))    // 153600

template <int NPROD, int OUTM>
__global__ __launch_bounds__(512, 1) void mma_gemm(
    const __half* __restrict__ Ah, const __half* __restrict__ Al,
    const __half* __restrict__ Bh,
    const float* __restrict__ bias, int biasMode,
    float* __restrict__ Cf, __half* __restrict__ Ch, __half* __restrict__ Cl,
    int ldA, int ldB, int ldC, int K, float alpha,
    long long sA, long long sB, long long sC)
{
    constexpr int NSTG = (NPROD == 1) ? 4 : 3;
    constexpr uint32_t STAGE = (NPROD == 1) ? (APLANE + BPLANE) : (2 * APLANE + BPLANE);
    constexpr uint32_t BOFF  = (NPROD == 1) ? APLANE : 2 * APLANE;

    extern __shared__ __align__(16) uint32_t sm[];
    const uint32_t sbase = smem_u32(sm);

    const int bz = blockIdx.z;
    Ah += (long long)bz * sA;
    if (NPROD >= 2) Al += (long long)bz * sA;
    Bh += (long long)bz * sB;

    const int m0 = blockIdx.y * 256;
    const int n0 = blockIdx.x * 128;
    const int tid  = threadIdx.x;
    const int wid  = tid >> 5, lane = tid & 31;
    const int wm   = wid >> 2, wn = wid & 3;      // 4x4 warps, tile 64x32
    const int g    = lane >> 2, t = lane & 3;

    // A loader: 2 threads/row (256 rows), 32B each
    const int arow = tid >> 1;
    const int aseg = (tid & 1) * 32;
    const char* gAh = (const char*)(Ah + (long long)(m0 + arow) * ldA) + aseg;
    const char* gAl = (NPROD >= 2)
        ? (const char*)(Al + (long long)(m0 + arow) * ldA) + aseg : nullptr;
    const uint32_t dstA = sbase + arow * RSTRIDE + aseg;
    // B loader: 4 threads/row (128 rows), 16B each
    const int brow = tid >> 2;
    const int bseg = (tid & 3) * 16;
    const char* gBh = (const char*)(Bh + (long long)(n0 + brow) * ldB) + bseg;
    const uint32_t dstB = sbase + brow * RSTRIDE + bseg;

    // ldmatrix per-lane base offsets (within a plane)
    const uint32_t a_off = (uint32_t)(wm * 64 + (lane & 15)) * RSTRIDE
                         + (uint32_t)(lane >> 4) * 16u;
    const uint32_t b_off = (uint32_t)(wn * 32 + (lane & 7) + ((lane >> 4) & 1) * 8) * RSTRIDE
                         + (uint32_t)((lane >> 3) & 1) * 16u;

    float acc[4][4][4];
#pragma unroll
    for (int i = 0; i < 4; i++)
#pragma unroll
        for (int j = 0; j < 4; j++)
#pragma unroll
            for (int e = 0; e < 4; e++) acc[i][j][e] = 0.0f;

    const int NCH = K >> 5;

    auto PREF = [&](int chv) {
        const uint32_t so = (uint32_t)(chv % NSTG) * STAGE;
        const long long go = (long long)chv * 64;
        cpa16(dstA + so,      gAh + go);
        cpa16(dstA + so + 16, gAh + go + 16);
        if (NPROD >= 2) {
            cpa16(dstA + so + APLANE,      gAl + go);
            cpa16(dstA + so + APLANE + 16, gAl + go + 16);
        }
        cpa16(dstB + so + BOFF, gBh + go);
    };

    auto COMPUTE = [&](int ch) {
        const uint32_t sb = sbase + (uint32_t)(ch % NSTG) * STAGE;
        const uint32_t aA  = sb + a_off;
        const uint32_t aAl = sb + APLANE + a_off;
        const uint32_t aB  = sb + BOFF + b_off;
#pragma unroll
        for (int ks = 0; ks < 2; ks++) {
            const uint32_t ko = ks * 32;
            uint32_t bh[4][2];
            ldsm_x4(bh[0][0], bh[0][1], bh[1][0], bh[1][1], aB + ko);
            ldsm_x4(bh[2][0], bh[2][1], bh[3][0], bh[3][1], aB + 16 * RSTRIDE + ko);
#pragma unroll
            for (int mi = 0; mi < 4; mi++) {
                uint32_t ah[4];
                ldsm_x4(ah[0], ah[1], ah[2], ah[3], aA + mi * 16 * RSTRIDE + ko);
#pragma unroll
                for (int ni = 0; ni < 4; ni++)
                    MMA_F16(acc[mi][ni], ah[0], ah[1], ah[2], ah[3], bh[ni][0], bh[ni][1]);
                if (NPROD >= 2) {
                    uint32_t al[4];
                    ldsm_x4(al[0], al[1], al[2], al[3], aAl + mi * 16 * RSTRIDE + ko);
#pragma unroll
                    for (int ni = 0; ni < 4; ni++)
                        MMA_F16(acc[mi][ni], al[0], al[1], al[2], al[3], bh[ni][0], bh[ni][1]);
                }
            }
        }
    };

    {
        const int npre = (NCH < NSTG - 1) ? NCH : (NSTG - 1);
        for (int i = 0; i < npre; i++) { PREF(i); CP_COMMIT(); }
    }
    for (int ch = 0; ch < NCH; ch++) {
        int w = NSTG - 2;
        const int rem = NCH - 1 - ch;
        if (rem < w) w = rem;
        if (w <= 0)      CP_WAIT0();
        else if (w == 1) CP_WAIT1();
        else             CP_WAIT2();
        __syncthreads();
        if (ch + NSTG - 1 < NCH) { PREF(ch + NSTG - 1); CP_COMMIT(); }
        COMPUTE(ch);
    }

    // ---------------- epilogue ----------------
    float*  CfB = Cf + (long long)bz * sC;
    __half* ChB = Ch + (long long)bz * sC;
    __half* ClB = Cl + (long long)bz * sC;

#pragma unroll
    for (int mi = 0; mi < 4; mi++) {
#pragma unroll
        for (int ni = 0; ni < 4; ni++) {
            const int r0 = m0 + wm * 64 + mi * 16 + g;
            const int c  = n0 + wn * 32 + ni * 8 + t * 2;
            float v0 = acc[mi][ni][0] * alpha, v1 = acc[mi][ni][1] * alpha;
            float v2 = acc[mi][ni][2] * alpha, v3 = acc[mi][ni][3] * alpha;
            if (bias) {
                if (biasMode == 0) {
                    const float b0 = bias[c], b1 = bias[c + 1];
                    v0 += b0; v1 += b1; v2 += b0; v3 += b1;
                } else {
                    const float br0 = bias[r0], br8 = bias[r0 + 8];
                    v0 += br0; v1 += br0; v2 += br8; v3 += br8;
                }
            }
            if (OUTM == 0) {
                *(float2*)&CfB[(long long)r0 * ldC + c]       = make_float2(v0, v1);
                *(float2*)&CfB[(long long)(r0 + 8) * ldC + c] = make_float2(v2, v3);
            } else if (OUTM == 1) {
                __half2 h0, l0, h1, l1;
                split2(v0, v1, h0, l0);
                split2(v2, v3, h1, l1);
                ((__half2*)ChB)[((long long)r0 * ldC + c) >> 1]       = h0;
                ((__half2*)ClB)[((long long)r0 * ldC + c) >> 1]       = l0;
                ((__half2*)ChB)[((long long)(r0 + 8) * ldC + c) >> 1] = h1;
                ((__half2*)ClB)[((long long)(r0 + 8) * ldC + c) >> 1] = l1;
            } else {
                ((__half2*)ChB)[((long long)r0 * ldC + c) >> 1]       = __floats2half2_rn(v0, v1);
                ((__half2*)ChB)[((long long)(r0 + 8) * ldC + c) >> 1] = __floats2half2_rn(v2, v3);
            }
        }
    }
}

// ---------------- fp32 -> fp16 ----------------
__global__ __launch_bounds__(256) void tohalf_kernel(
    const float* __restrict__ in, __half* __restrict__ oh, int n4)
{
    const int i = blockIdx.x * 256 + threadIdx.x;
    if (i >= n4) return;
    float4 v = ((const float4*)in)[i];
    ((__half2*)oh)[i * 2]     = __floats2half2_rn(v.x, v.y);
    ((__half2*)oh)[i * 2 + 1] = __floats2half2_rn(v.z, v.w);
}

// ---------------- concat two 512-float biases ----------------
__global__ __launch_bounds__(256) void bcat_kernel(
    const float* __restrict__ a, const float* __restrict__ b,
    float* __restrict__ o)
{
    const int i = blockIdx.x * 256 + threadIdx.x;
    o[i] = (i < 512) ? a[i] : b[i - 512];
}

// ------------- transpose: fp32 [R][C] -> fp16 [C][R] ----------
__global__ __launch_bounds__(256) void tsplit_kernel(
    const float* __restrict__ in, __half* __restrict__ oh,
    int R, int C, long long sI, long long sO)
{
    __shared__ float tile[32][33];
    const int z = blockIdx.z;
    in += (long long)z * sI;
    oh += (long long)z * sO;
    const int c0 = blockIdx.x * 32, r0 = blockIdx.y * 32;
    const int tx = threadIdx.x & 31, ty = threadIdx.x >> 5;

#pragma unroll
    for (int i = 0; i < 4; i++)
        tile[ty + i * 8][tx] = in[(long long)(r0 + ty + i * 8) * C + c0 + tx];
    __syncthreads();
#pragma unroll
    for (int i = 0; i < 4; i++) {
        const float v = tile[tx][ty + i * 8];
        oh[(long long)(c0 + ty + i * 8) * R + r0 + tx] = __float2half_rn(v);
    }
}

// -------- softmax, in-place on fp16 plane (row = 2048) --------
__device__ __forceinline__ float warpMax(float v) {
#pragma unroll
    for (int o = 16; o > 0; o >>= 1) v = fmaxf(v, __shfl_xor_sync(0xffffffffu, v, o));
    return v;
}
__device__ __forceinline__ float warpSum(float v) {
#pragma unroll
    for (int o = 16; o > 0; o >>= 1) v += __shfl_xor_sync(0xffffffffu, v, o);
    return v;
}

__global__ __launch_bounds__(256) void softmax_kernel(__half* __restrict__ H)
{
    const long long base = (long long)blockIdx.x * 2048;
    __half2* rh = (__half2*)(H + base);
    const int tid = threadIdx.x;
    const int lane = tid & 31, wid = tid >> 5;
    __shared__ float sh[8];

    float v[8];
#pragma unroll
    for (int j = 0; j < 4; j++) {
        const __half2 hv = rh[tid * 4 + j];
        v[2*j]   = __half2float(hv.x);
        v[2*j+1] = __half2float(hv.y);
    }

    float m = v[0];
#pragma unroll
    for (int i = 1; i < 8; i++) m = fmaxf(m, v[i]);
    m = warpMax(m);
    if (lane == 0) sh[wid] = m;
    __syncthreads();
    m = sh[0];
#pragma unroll
    for (int w = 1; w < 8; w++) m = fmaxf(m, sh[w]);

    float e[8];
    float s = 0.0f;
#pragma unroll
    for (int i = 0; i < 8; i++) { e[i] = __expf(v[i] - m); s += e[i]; }
    s = warpSum(s);
    __syncthreads();
    if (lane == 0) sh[wid] = s;
    __syncthreads();
    float tot = 0.0f;
#pragma unroll
    for (int w = 0; w < 8; w++) tot += sh[w];
    const float inv = 1.0f / tot;

#pragma unroll
    for (int j = 0; j < 4; j++)
        rh[tid * 4 + j] = __floats2half2_rn(e[2*j] * inv, e[2*j+1] * inv);
}

// ---------------- fused add(+gelu)+LN ----------------
template <int MODE, bool WF32>
__global__ __launch_bounds__(128) void rowln_kernel(
    const float* __restrict__ X, const float* __restrict__ Y,
    const float* __restrict__ g, const float* __restrict__ b,
    float* __restrict__ Of, __half* __restrict__ Oh, __half* __restrict__ Ol)
{
    const long long row = (long long)blockIdx.x * 512;
    const int tid = threadIdx.x;
    const int lane = tid & 31, wid = tid >> 5;
    __shared__ float s1[4], s2[4];

    float t[4];
    float sum = 0.0f, sq = 0.0f;
#pragma unroll
    for (int i = 0; i < 4; i++) {
        const int c = tid + i * 128;
        float u = X[row + c] + Y[row + c];
        if (MODE == 1) u = 0.5f * u * (1.0f + erff(u * 0.7071067811865476f));
        t[i] = u;
        sum += u;
        sq += u * u;
    }
    sum = warpSum(sum);
    sq = warpSum(sq);
    if (lane == 0) { s1[wid] = sum; s2[wid] = sq; }
    __syncthreads();
    float ts = 0.0f, tq = 0.0f;
#pragma unroll
    for (int w = 0; w < 4; w++) { ts += s1[w]; tq += s2[w]; }
    const float mean = ts * (1.0f / 512.0f);
    const float var = tq * (1.0f / 512.0f) - mean * mean;
    const float inv = rsqrtf(var + 1e-5f);

#pragma unroll
    for (int i = 0; i < 4; i++) {
        const int c = tid + i * 128;
        const float o = (t[i] - mean) * inv * g[c] + b[c];
        if (WF32) Of[row + c] = o;
        const __half h = __float2half_rn(o);
        Oh[row + c] = h;
        Ol[row + c] = __float2half_rn(o - __half2float(h));
    }
}

// ---------------- host ----------------
template <typename T>
static T* symaddr(const void* sym)
{
    void* p = nullptr;
    cudaGetSymbolAddress(&p, sym);
    return (T*)p;
}

extern "C" void kernel_launch(void* const* d_in, const int* in_sizes, int n_in,
                              void* d_out, int out_size)
{
    const float* x    = (const float*)d_in[0];
    const float* Wq   = (const float*)d_in[1];
    const float* bq   = (const float*)d_in[2];
    const float* Wk   = (const float*)d_in[3];
    const float* bk   = (const float*)d_in[4];
    const float* Wv   = (const float*)d_in[5];
    const float* bv   = (const float*)d_in[6];
    const float* ln0g = (const float*)d_in[7];
    const float* ln0b = (const float*)d_in[8];
    const float* W1   = (const float*)d_in[9];
    const float* b1   = (const float*)d_in[10];
    const float* ln1g = (const float*)d_in[11];
    const float* ln1b = (const float*)d_in[12];
    const float* W2   = (const float*)d_in[13];
    const float* b2   = (const float*)d_in[14];
    const float* ln2g = (const float*)d_in[15];
    const float* ln2b = (const float*)d_in[16];
    const float* W3   = (const float*)d_in[17];
    const float* b3   = (const float*)d_in[18];
    float* out = (float*)d_out;

    __half* xh  = symaddr<__half>(g_xh);
    __half* qkh = symaddr<__half>(g_qkh);
    __half* vth = symaddr<__half>(g_vth);
    __half* onh = symaddr<__half>(g_onh);  __half* onl = symaddr<__half>(g_onl);
    __half* hh  = symaddr<__half>(g_hh);   __half* hl  = symaddr<__half>(g_hl);
    __half* h2h = symaddr<__half>(g_h2h);  __half* h2l = symaddr<__half>(g_h2l);
    __half* sh_ = symaddr<__half>(g_sh);
    __half* wth = symaddr<__half>(g_wth);
    float* bqk = symaddr<float>(g_bqk);
    float* tt  = symaddr<float>(g_t);
    float* on  = symaddr<float>(g_on);

    cudaFuncSetAttribute(mma_gemm<1,0>, cudaFuncAttributeMaxDynamicSharedMemorySize, SMEM_P1);
    cudaFuncSetAttribute(mma_gemm<1,2>, cudaFuncAttributeMaxDynamicSharedMemorySize, SMEM_P1);
    cudaFuncSetAttribute(mma_gemm<2,0>, cudaFuncAttributeMaxDynamicSharedMemorySize, SMEM_P2);

    const long long sQK = 2048LL * 1024;   // per-batch rows in qk buffer
    const long long sSD = 2048LL * 512;
    const long long sSS = 2048LL * 2048;
    const long long WSZ = 512LL * 512;
    const float scale = 0.044194173824159216f;   // 1/sqrt(512)

    dim3 gW(16, 16, 1);
    dim3 bT(256);
    dim3 gQK(8, 64, 1);        // N=1024, M=16384
    dim3 gScores(16, 8, 8);    // per batch: N=2048, M=2048 (256-tiles)
    dim3 gVt(128, 2, 1);       // N=16384, M=512
    dim3 gAtt(4, 8, 8);
    dim3 gProj(4, 64, 1);      // N=512, M=16384

    // 1-4: q/k inputs (combined)
    tohalf_kernel<<<MTOT / 1024, 256>>>(x, xh, MTOT / 4);
    tsplit_kernel<<<gW, bT>>>(Wq, wth + 0 * WSZ, 512, 512, 0, 0);
    tsplit_kernel<<<gW, bT>>>(Wk, wth + 1 * WSZ, 512, 512, 0, 0);
    bcat_kernel<<<4, 256>>>(bq, bk, bqk);

    // 5: fused q|k = x @ [Wq Wk] (fp16 out, ldC=1024)
    mma_gemm<1,2><<<gQK, 512, SMEM_P1>>>(xh, nullptr, wth,
        bqk, 0, nullptr, qkh, nullptr, 512, 512, 1024, 512, 1.0f, 0, 0, 0);

    // 6: scores = q @ k^T * scale (ncu profiles this launch)
    mma_gemm<1,2><<<gScores, 512, SMEM_P1>>>(qkh, nullptr, qkh + 512,
        nullptr, 0, nullptr, sh_, nullptr, 1024, 1024, 2048, 512, scale,
        sQK, sQK, sSS);

    // 7: softmax in-place
    softmax_kernel<<<16384, 256>>>(sh_);

    // 8-9: v^T = Wv^T @ x^T (row bias bv), fp16 out [512][16384]
    tsplit_kernel<<<gW, bT>>>(Wv, wth + 2 * WSZ, 512, 512, 0, 0);
    mma_gemm<1,2><<<gVt, 512, SMEM_P1>>>(wth + 2 * WSZ, nullptr, xh,
        bv, 1, nullptr, vth, nullptr, 512, 512, 16384, 512, 1.0f, 0, 0, 0);

    // 10: att = w @ v  (B = v^T rows, ldB=16384, per-batch col offset 2048)
    mma_gemm<1,0><<<gAtt, 512, SMEM_P1>>>(sh_, nullptr, vth,
        nullptr, 0, tt, nullptr, nullptr, 2048, 16384, 512, 2048, 1.0f,
        sSS, 2048, sSD);

    // 11: out_nxt = LN(x + att)
    rowln_kernel<0, true><<<16384, 128>>>(x, tt, ln0g, ln0b, on, onh, onl);

    // 12-14: h1 (NPROD=2)
    tsplit_kernel<<<gW, bT>>>(W1, wth + 3 * WSZ, 512, 512, 0, 0);
    mma_gemm<2,0><<<gProj, 512, SMEM_P2>>>(onh, onl, wth + 3 * WSZ,
        b1, 0, tt, nullptr, nullptr, 512, 512, 512, 512, 1.0f, 0, 0, 0);
    rowln_kernel<1, false><<<16384, 128>>>(on, tt, ln1g, ln1b, nullptr, hh, hl);

    // 15-17: h2 (NPROD=2)
    tsplit_kernel<<<gW, bT>>>(W2, wth + 4 * WSZ, 512, 512, 0, 0);
    mma_gemm<2,0><<<gProj, 512, SMEM_P2>>>(hh, hl, wth + 4 * WSZ,
        b2, 0, tt, nullptr, nullptr, 512, 512, 512, 512, 1.0f, 0, 0, 0);
    rowln_kernel<1, false><<<16384, 128>>>(on, tt, ln2g, ln2b, nullptr, h2h, h2l);

    // 18-19: out = h2 @ W3 + b3 (NPROD=2)
    tsplit_kernel<<<gW, bT>>>(W3, wth + 5 * WSZ, 512, 512, 0, 0);
    mma_gemm<2,0><<<gProj, 512, SMEM_P2>>>(h2h, h2l, wth + 5 * WSZ,
        b3, 0, out, nullptr, nullptr, 512, 512, 512, 512, 1.0f, 0, 0, 0);
}

// round 11
// speedup vs baseline: 1.0518x; 1.0201x over previous
#include <cuda_runtime.h>
#include <cuda_fp16.h>
#include <math.h>
#include <stdint.h>

// ===========================================================================
// AttentionBlock B=8,S=2048,D=512 — mma.sync fp16, precision-tiered GEMMs
// R11: R8 GEMM core (128x128, BK=32, 2 CTA/SM) + generalized strides,
//      fp16-pair residual path (no fp32 scratch), att fp16 hi-only,
//      direct v^T GEMM.
// ===========================================================================

#define MTOT (16384 * 512)
__device__ __half g_xh[MTOT];
__device__ __half g_qh[MTOT];
__device__ __half g_kh[MTOT];
__device__ __half g_vth[MTOT];                      // v^T [512][16384]
__device__ __half g_ath[MTOT];                      // att fp16
__device__ __half g_onh[MTOT], g_onl[MTOT];
__device__ __half g_th[MTOT],  g_tl[MTOT];          // FFN pre-activation pair
__device__ __half g_hh[MTOT],  g_hl[MTOT];          // h1
__device__ __half g_h2h[MTOT], g_h2l[MTOT];         // h2
__device__ __half g_sh[8LL * 2048 * 2048];
__device__ __half g_wth[6 * 512 * 512];             // W^T planes

// ---------------- helpers ----------------
__device__ __forceinline__ uint32_t smem_u32(const void* p) {
    uint32_t a;
    asm("{ .reg .u64 t; cvta.to.shared.u64 t, %1; cvt.u32.u64 %0, t; }"
        : "=r"(a) : "l"(p));
    return a;
}
__device__ __forceinline__ void cpa16(uint32_t dst, const void* src) {
    asm volatile("cp.async.cg.shared.global [%0], [%1], 16;"
                 :: "r"(dst), "l"(src) : "memory");
}
#define CP_COMMIT() asm volatile("cp.async.commit_group;" ::: "memory")
#define CP_WAIT0()  asm volatile("cp.async.wait_group 0;"  ::: "memory")
#define CP_WAIT1()  asm volatile("cp.async.wait_group 1;"  ::: "memory")
#define CP_WAIT2()  asm volatile("cp.async.wait_group 2;"  ::: "memory")

#define MMA_F16(c, a0, a1, a2, a3, b0, b1)                                    \
    asm volatile("mma.sync.aligned.m16n8k16.row.col.f32.f16.f16.f32 "         \
        "{%0,%1,%2,%3}, {%4,%5,%6,%7}, {%8,%9}, {%0,%1,%2,%3};"               \
        : "+f"((c)[0]), "+f"((c)[1]), "+f"((c)[2]), "+f"((c)[3])              \
        : "r"(a0), "r"(a1), "r"(a2), "r"(a3), "r"(b0), "r"(b1))

__device__ __forceinline__ void ldsm_x4(uint32_t& r0, uint32_t& r1,
                                        uint32_t& r2, uint32_t& r3, uint32_t a) {
    asm volatile("ldmatrix.sync.aligned.m8n8.x4.shared.b16 {%0,%1,%2,%3}, [%4];"
                 : "=r"(r0), "=r"(r1), "=r"(r2), "=r"(r3) : "r"(a));
}

__device__ __forceinline__ void split2(float a, float b, __half2& h, __half2& l) {
    h = __floats2half2_rn(a, b);
    l = __floats2half2_rn(a - __half2float(h.x), b - __half2float(h.y));
}

// ---------------- GEMM ----------------
// Block tile 128x128, BK=32, 8 warps (2x4), warp tile 64x32, 256 thr, 2 CTA/SM.
// NPROD=1: planes [A,B],      4-stage
// NPROD=2: planes [Ah,Al,Bh], 3-stage
// OUTM: 0 = fp32 C; 1 = fp16 pair; 2 = fp16 hi only.  biasMode: 0=col, 1=row.
#define RSTRIDE 80
#define PLANE_B 10240
#define SMEM_P1 (4 * 2 * PLANE_B)   // 81920
#define SMEM_P2 (3 * 3 * PLANE_B)   // 92160

template <int NPROD, int OUTM>
__global__ __launch_bounds__(256, 2) void mma_gemm(
    const __half* __restrict__ Ah, const __half* __restrict__ Al,
    const __half* __restrict__ Bh,
    const float* __restrict__ bias, int biasMode,
    float* __restrict__ Cf, __half* __restrict__ Ch, __half* __restrict__ Cl,
    int ldA, int ldB, int ldC, int K, float alpha,
    long long sA, long long sB, long long sC)
{
    constexpr int NSTG = (NPROD == 1) ? 4 : 3;
    constexpr uint32_t STAGE = (NPROD == 1) ? 2 * PLANE_B : 3 * PLANE_B;
    constexpr uint32_t BOFF  = (NPROD == 1) ? PLANE_B : 2 * PLANE_B;

    extern __shared__ __align__(16) uint32_t sm[];
    const uint32_t sbase = smem_u32(sm);

    const int bz = blockIdx.z;
    Ah += (long long)bz * sA;
    if (NPROD >= 2) Al += (long long)bz * sA;
    Bh += (long long)bz * sB;

    const int m0 = blockIdx.y * 128;
    const int n0 = blockIdx.x * 128;
    const int tid  = threadIdx.x;
    const int wid  = tid >> 5, lane = tid & 31;
    const int wm   = wid >> 2, wn = wid & 3;      // warp tile 64 x 32
    const int g    = lane >> 2, t = lane & 3;

    // loader: 2 threads per row, 2 x 16B segments each, per plane
    const int lrow = tid >> 1;
    const int lseg = (tid & 1) * 2;
    const char* gAh = (const char*)(Ah + (long long)(m0 + lrow) * ldA) + lseg * 16;
    const char* gAl = (NPROD >= 2)
        ? (const char*)(Al + (long long)(m0 + lrow) * ldA) + lseg * 16 : nullptr;
    const char* gBh = (const char*)(Bh + (long long)(n0 + lrow) * ldB) + lseg * 16;
    const uint32_t dst0 = sbase + lrow * RSTRIDE + lseg * 16;

    // ldmatrix per-lane base offsets (within a plane)
    const uint32_t a_off = (uint32_t)(wm * 64 + (lane & 15)) * RSTRIDE
                         + (uint32_t)(lane >> 4) * 16u;
    const uint32_t b_off = (uint32_t)(wn * 32 + (lane & 7) + ((lane >> 4) & 1) * 8) * RSTRIDE
                         + (uint32_t)((lane >> 3) & 1) * 16u;

    float acc[4][4][4];
#pragma unroll
    for (int i = 0; i < 4; i++)
#pragma unroll
        for (int j = 0; j < 4; j++)
#pragma unroll
            for (int e = 0; e < 4; e++) acc[i][j][e] = 0.0f;

    const int NCH = K >> 5;

    auto PREF = [&](int chv) {
        const uint32_t so = (uint32_t)(chv % NSTG) * STAGE;
        const long long go = (long long)chv * 64;
        cpa16(dst0 + so,      gAh + go);
        cpa16(dst0 + so + 16, gAh + go + 16);
        if (NPROD >= 2) {
            cpa16(dst0 + so + PLANE_B,      gAl + go);
            cpa16(dst0 + so + PLANE_B + 16, gAl + go + 16);
        }
        cpa16(dst0 + so + BOFF,      gBh + go);
        cpa16(dst0 + so + BOFF + 16, gBh + go + 16);
    };

    auto COMPUTE = [&](int ch) {
        const uint32_t sb = sbase + (uint32_t)(ch % NSTG) * STAGE;
        const uint32_t aA  = sb + a_off;
        const uint32_t aAl = sb + PLANE_B + a_off;
        const uint32_t aB  = sb + BOFF + b_off;
#pragma unroll
        for (int ks = 0; ks < 2; ks++) {
            const uint32_t ko = ks * 32;
            uint32_t bh[4][2];
            ldsm_x4(bh[0][0], bh[0][1], bh[1][0], bh[1][1], aB + ko);
            ldsm_x4(bh[2][0], bh[2][1], bh[3][0], bh[3][1], aB + 16 * RSTRIDE + ko);
#pragma unroll
            for (int mi = 0; mi < 4; mi++) {
                uint32_t ah[4];
                ldsm_x4(ah[0], ah[1], ah[2], ah[3], aA + mi * 16 * RSTRIDE + ko);
#pragma unroll
                for (int ni = 0; ni < 4; ni++)
                    MMA_F16(acc[mi][ni], ah[0], ah[1], ah[2], ah[3], bh[ni][0], bh[ni][1]);
                if (NPROD >= 2) {
                    uint32_t al[4];
                    ldsm_x4(al[0], al[1], al[2], al[3], aAl + mi * 16 * RSTRIDE + ko);
#pragma unroll
                    for (int ni = 0; ni < 4; ni++)
                        MMA_F16(acc[mi][ni], al[0], al[1], al[2], al[3], bh[ni][0], bh[ni][1]);
                }
            }
        }
    };

    {
        const int npre = (NCH < NSTG - 1) ? NCH : (NSTG - 1);
        for (int i = 0; i < npre; i++) { PREF(i); CP_COMMIT(); }
    }
    for (int ch = 0; ch < NCH; ch++) {
        int w = NSTG - 2;
        const int rem = NCH - 1 - ch;
        if (rem < w) w = rem;
        if (w <= 0)      CP_WAIT0();
        else if (w == 1) CP_WAIT1();
        else             CP_WAIT2();
        __syncthreads();
        if (ch + NSTG - 1 < NCH) { PREF(ch + NSTG - 1); CP_COMMIT(); }
        COMPUTE(ch);
    }

    // ---------------- epilogue ----------------
    float*  CfB = Cf + (long long)bz * sC;
    __half* ChB = Ch + (long long)bz * sC;
    __half* ClB = Cl + (long long)bz * sC;

#pragma unroll
    for (int mi = 0; mi < 4; mi++) {
#pragma unroll
        for (int ni = 0; ni < 4; ni++) {
            const int r0 = m0 + wm * 64 + mi * 16 + g;
            const int c  = n0 + wn * 32 + ni * 8 + t * 2;
            float v0 = acc[mi][ni][0] * alpha, v1 = acc[mi][ni][1] * alpha;
            float v2 = acc[mi][ni][2] * alpha, v3 = acc[mi][ni][3] * alpha;
            if (bias) {
                if (biasMode == 0) {
                    const float b0 = bias[c], b1 = bias[c + 1];
                    v0 += b0; v1 += b1; v2 += b0; v3 += b1;
                } else {
                    const float br0 = bias[r0], br8 = bias[r0 + 8];
                    v0 += br0; v1 += br0; v2 += br8; v3 += br8;
                }
            }
            if (OUTM == 0) {
                *(float2*)&CfB[(long long)r0 * ldC + c]       = make_float2(v0, v1);
                *(float2*)&CfB[(long long)(r0 + 8) * ldC + c] = make_float2(v2, v3);
            } else if (OUTM == 1) {
                __half2 h0, l0, h1, l1;
                split2(v0, v1, h0, l0);
                split2(v2, v3, h1, l1);
                ((__half2*)ChB)[((long long)r0 * ldC + c) >> 1]       = h0;
                ((__half2*)ClB)[((long long)r0 * ldC + c) >> 1]       = l0;
                ((__half2*)ChB)[((long long)(r0 + 8) * ldC + c) >> 1] = h1;
                ((__half2*)ClB)[((long long)(r0 + 8) * ldC + c) >> 1] = l1;
            } else {
                ((__half2*)ChB)[((long long)r0 * ldC + c) >> 1]       = __floats2half2_rn(v0, v1);
                ((__half2*)ChB)[((long long)(r0 + 8) * ldC + c) >> 1] = __floats2half2_rn(v2, v3);
            }
        }
    }
}

// ---------------- fp32 -> fp16 ----------------
__global__ __launch_bounds__(256) void tohalf_kernel(
    const float* __restrict__ in, __half* __restrict__ oh, int n4)
{
    const int i = blockIdx.x * 256 + threadIdx.x;
    if (i >= n4) return;
    float4 v = ((const float4*)in)[i];
    ((__half2*)oh)[i * 2]     = __floats2half2_rn(v.x, v.y);
    ((__half2*)oh)[i * 2 + 1] = __floats2half2_rn(v.z, v.w);
}

// ------------- transpose: fp32 [R][C] -> fp16 [C][R] ----------
__global__ __launch_bounds__(256) void tsplit_kernel(
    const float* __restrict__ in, __half* __restrict__ oh,
    int R, int C, long long sI, long long sO)
{
    __shared__ float tile[32][33];
    const int z = blockIdx.z;
    in += (long long)z * sI;
    oh += (long long)z * sO;
    const int c0 = blockIdx.x * 32, r0 = blockIdx.y * 32;
    const int tx = threadIdx.x & 31, ty = threadIdx.x >> 5;

#pragma unroll
    for (int i = 0; i < 4; i++)
        tile[ty + i * 8][tx] = in[(long long)(r0 + ty + i * 8) * C + c0 + tx];
    __syncthreads();
#pragma unroll
    for (int i = 0; i < 4; i++) {
        const float v = tile[tx][ty + i * 8];
        oh[(long long)(c0 + ty + i * 8) * R + r0 + tx] = __float2half_rn(v);
    }
}

// -------- softmax, in-place on fp16 plane (row = 2048) --------
__device__ __forceinline__ float warpMax(float v) {
#pragma unroll
    for (int o = 16; o > 0; o >>= 1) v = fmaxf(v, __shfl_xor_sync(0xffffffffu, v, o));
    return v;
}
__device__ __forceinline__ float warpSum(float v) {
#pragma unroll
    for (int o = 16; o > 0; o >>= 1) v += __shfl_xor_sync(0xffffffffu, v, o);
    return v;
}

__global__ __launch_bounds__(256) void softmax_kernel(__half* __restrict__ H)
{
    const long long base = (long long)blockIdx.x * 2048;
    __half2* rh = (__half2*)(H + base);
    const int tid = threadIdx.x;
    const int lane = tid & 31, wid = tid >> 5;
    __shared__ float sh[8];

    float v[8];
#pragma unroll
    for (int j = 0; j < 4; j++) {
        const __half2 hv = rh[tid * 4 + j];
        v[2*j]   = __half2float(hv.x);
        v[2*j+1] = __half2float(hv.y);
    }

    float m = v[0];
#pragma unroll
    for (int i = 1; i < 8; i++) m = fmaxf(m, v[i]);
    m = warpMax(m);
    if (lane == 0) sh[wid] = m;
    __syncthreads();
    m = sh[0];
#pragma unroll
    for (int w = 1; w < 8; w++) m = fmaxf(m, sh[w]);

    float e[8];
    float s = 0.0f;
#pragma unroll
    for (int i = 0; i < 8; i++) { e[i] = __expf(v[i] - m); s += e[i]; }
    s = warpSum(s);
    __syncthreads();
    if (lane == 0) sh[wid] = s;
    __syncthreads();
    float tot = 0.0f;
#pragma unroll
    for (int w = 0; w < 8; w++) tot += sh[w];
    const float inv = 1.0f / tot;

#pragma unroll
    for (int j = 0; j < 4; j++)
        rh[tid * 4 + j] = __floats2half2_rn(e[2*j] * inv, e[2*j+1] * inv);
}

// ---------------- fused add(+gelu)+LN, fp16-pair I/O ----------------
// X: XPAIR ? (Xh + Xl) : fp32 Xf.  Y: YPAIR ? (Yh + Yl) : Yh (hi only).
// Output: fp16 pair (Oh, Ol).
template <int MODE, bool XPAIR, bool YPAIR>
__global__ __launch_bounds__(128) void rowln_kernel(
    const float* __restrict__ Xf,
    const __half* __restrict__ Xh, const __half* __restrict__ Xl,
    const __half* __restrict__ Yh, const __half* __restrict__ Yl,
    const float* __restrict__ g, const float* __restrict__ b,
    __half* __restrict__ Oh, __half* __restrict__ Ol)
{
    const long long row = (long long)blockIdx.x * 512;
    const int tid = threadIdx.x;
    const int lane = tid & 31, wid = tid >> 5;
    __shared__ float s1[4], s2[4];

    float t[4];
    float sum = 0.0f, sq = 0.0f;
#pragma unroll
    for (int i = 0; i < 4; i++) {
        const int c = tid + i * 128;
        float xv;
        if (XPAIR) xv = __half2float(Xh[row + c]) + __half2float(Xl[row + c]);
        else       xv = Xf[row + c];
        float yv = __half2float(Yh[row + c]);
        if (YPAIR)  yv += __half2float(Yl[row + c]);
        float u = xv + yv;
        if (MODE == 1) u = 0.5f * u * (1.0f + erff(u * 0.7071067811865476f));
        t[i] = u;
        sum += u;
        sq += u * u;
    }
    sum = warpSum(sum);
    sq = warpSum(sq);
    if (lane == 0) { s1[wid] = sum; s2[wid] = sq; }
    __syncthreads();
    float ts = 0.0f, tq = 0.0f;
#pragma unroll
    for (int w = 0; w < 4; w++) { ts += s1[w]; tq += s2[w]; }
    const float mean = ts * (1.0f / 512.0f);
    const float var = tq * (1.0f / 512.0f) - mean * mean;
    const float inv = rsqrtf(var + 1e-5f);

#pragma unroll
    for (int i = 0; i < 4; i++) {
        const int c = tid + i * 128;
        const float o = (t[i] - mean) * inv * g[c] + b[c];
        const __half h = __float2half_rn(o);
        Oh[row + c] = h;
        Ol[row + c] = __float2half_rn(o - __half2float(h));
    }
}

// ---------------- host ----------------
template <typename T>
static T* symaddr(const void* sym)
{
    void* p = nullptr;
    cudaGetSymbolAddress(&p, sym);
    return (T*)p;
}

extern "C" void kernel_launch(void* const* d_in, const int* in_sizes, int n_in,
                              void* d_out, int out_size)
{
    const float* x    = (const float*)d_in[0];
    const float* Wq   = (const float*)d_in[1];
    const float* bq   = (const float*)d_in[2];
    const float* Wk   = (const float*)d_in[3];
    const float* bk   = (const float*)d_in[4];
    const float* Wv   = (const float*)d_in[5];
    const float* bv   = (const float*)d_in[6];
    const float* ln0g = (const float*)d_in[7];
    const float* ln0b = (const float*)d_in[8];
    const float* W1   = (const float*)d_in[9];
    const float* b1   = (const float*)d_in[10];
    const float* ln1g = (const float*)d_in[11];
    const float* ln1b = (const float*)d_in[12];
    const float* W2   = (const float*)d_in[13];
    const float* b2   = (const float*)d_in[14];
    const float* ln2g = (const float*)d_in[15];
    const float* ln2b = (const float*)d_in[16];
    const float* W3   = (const float*)d_in[17];
    const float* b3   = (const float*)d_in[18];
    float* out = (float*)d_out;

    __half* xh  = symaddr<__half>(g_xh);
    __half* qh  = symaddr<__half>(g_qh);
    __half* kh  = symaddr<__half>(g_kh);
    __half* vth = symaddr<__half>(g_vth);
    __half* ath = symaddr<__half>(g_ath);
    __half* onh = symaddr<__half>(g_onh);  __half* onl = symaddr<__half>(g_onl);
    __half* th  = symaddr<__half>(g_th);   __half* tl  = symaddr<__half>(g_tl);
    __half* hh  = symaddr<__half>(g_hh);   __half* hl  = symaddr<__half>(g_hl);
    __half* h2h = symaddr<__half>(g_h2h);  __half* h2l = symaddr<__half>(g_h2l);
    __half* sh_ = symaddr<__half>(g_sh);
    __half* wth = symaddr<__half>(g_wth);

    cudaFuncSetAttribute(mma_gemm<1,0>, cudaFuncAttributeMaxDynamicSharedMemorySize, SMEM_P1);
    cudaFuncSetAttribute(mma_gemm<1,2>, cudaFuncAttributeMaxDynamicSharedMemorySize, SMEM_P1);
    cudaFuncSetAttribute(mma_gemm<2,0>, cudaFuncAttributeMaxDynamicSharedMemorySize, SMEM_P2);
    cudaFuncSetAttribute(mma_gemm<2,1>, cudaFuncAttributeMaxDynamicSharedMemorySize, SMEM_P2);

    const long long sSD = 2048LL * 512;
    const long long sSS = 2048LL * 2048;
    const long long WSZ = 512LL * 512;
    const float scale = 0.044194173824159216f;   // 1/sqrt(512)

    dim3 gW(16, 16, 1);
    dim3 bT(256);
    dim3 gProj(4, 128, 1);     // N=512, M=16384
    dim3 gScores(16, 16, 8);   // per batch 2048x2048
    dim3 gVt(128, 4, 1);       // N=16384, M=512
    dim3 gAtt(4, 16, 8);

    // 1-3: q/k inputs
    tohalf_kernel<<<MTOT / 1024, 256>>>(x, xh, MTOT / 4);
    tsplit_kernel<<<gW, bT>>>(Wq, wth + 0 * WSZ, 512, 512, 0, 0);
    tsplit_kernel<<<gW, bT>>>(Wk, wth + 1 * WSZ, 512, 512, 0, 0);

    // 4-5: q, k (fp16, NPROD=1)
    mma_gemm<1,2><<<gProj, 256, SMEM_P1>>>(xh, nullptr, wth + 0 * WSZ,
        bq, 0, nullptr, qh, nullptr, 512, 512, 512, 512, 1.0f, 0, 0, 0);
    mma_gemm<1,2><<<gProj, 256, SMEM_P1>>>(xh, nullptr, wth + 1 * WSZ,
        bk, 0, nullptr, kh, nullptr, 512, 512, 512, 512, 1.0f, 0, 0, 0);

    // 6: scores = q @ k^T * scale (ncu profiles this launch)
    mma_gemm<1,2><<<gScores, 256, SMEM_P1>>>(qh, nullptr, kh,
        nullptr, 0, nullptr, sh_, nullptr, 512, 512, 2048, 512, scale,
        sSD, sSD, sSS);

    // 7: softmax in-place
    softmax_kernel<<<16384, 256>>>(sh_);

    // 8-9: v^T = Wv^T @ x^T (row bias bv) -> [512][16384] fp16
    tsplit_kernel<<<gW, bT>>>(Wv, wth + 2 * WSZ, 512, 512, 0, 0);
    mma_gemm<1,2><<<gVt, 256, SMEM_P1>>>(wth + 2 * WSZ, nullptr, xh,
        bv, 1, nullptr, vth, nullptr, 512, 512, 16384, 512, 1.0f, 0, 0, 0);

    // 10: att = w @ v -> fp16 hi only
    mma_gemm<1,2><<<gAtt, 256, SMEM_P1>>>(sh_, nullptr, vth,
        nullptr, 0, nullptr, ath, nullptr, 2048, 16384, 512, 2048, 1.0f,
        sSS, 2048, sSD);

    // 11: out_nxt = LN(x + att) -> pair
    rowln_kernel<0, false, false><<<16384, 128>>>(
        x, nullptr, nullptr, ath, nullptr, ln0g, ln0b, onh, onl);

    // 12-14: h1 = LN(gelu(on + on@W1 + b1))
    tsplit_kernel<<<gW, bT>>>(W1, wth + 3 * WSZ, 512, 512, 0, 0);
    mma_gemm<2,1><<<gProj, 256, SMEM_P2>>>(onh, onl, wth + 3 * WSZ,
        b1, 0, nullptr, th, tl, 512, 512, 512, 512, 1.0f, 0, 0, 0);
    rowln_kernel<1, true, true><<<16384, 128>>>(
        nullptr, onh, onl, th, tl, ln1g, ln1b, hh, hl);

    // 15-17: h2 = LN(gelu(on + h1@W2 + b2))
    tsplit_kernel<<<gW, bT>>>(W2, wth + 4 * WSZ, 512, 512, 0, 0);
    mma_gemm<2,1><<<gProj, 256, SMEM_P2>>>(hh, hl, wth + 4 * WSZ,
        b2, 0, nullptr, th, tl, 512, 512, 512, 512, 1.0f, 0, 0, 0);
    rowln_kernel<1, true, true><<<16384, 128>>>(
        nullptr, onh, onl, th, tl, ln2g, ln2b, h2h, h2l);

    // 18-19: out = h2 @ W3 + b3 (fp32)
    tsplit_kernel<<<gW, bT>>>(W3, wth + 5 * WSZ, 512, 512, 0, 0);
    mma_gemm<2,0><<<gProj, 256, SMEM_P2>>>(h2h, h2l, wth + 5 * WSZ,
        b3, 0, out, nullptr, nullptr, 512, 512, 512, 512, 1.0f, 0, 0, 0);
}

// round 12
// speedup vs baseline: 1.0734x; 1.0205x over previous
#include <cuda_runtime.h>
#include <cuda_fp16.h>
#include <math.h>
#include <stdint.h>

// ===========================================================================
// AttentionBlock B=8,S=2048,D=512 — mma.sync fp16, precision-tiered GEMMs
// R12: fp16-accumulator GEMM (3 CTA/SM, 24 warps) for q/k/v^T/scores;
//      fp32-acc GEMM for att + FFN. fp16-pair residual path.
// ===========================================================================

#define MTOT (16384 * 512)
__device__ __half g_xh[MTOT];
__device__ __half g_qh[MTOT];
__device__ __half g_kh[MTOT];
__device__ __half g_vth[MTOT];                      // v^T [512][16384]
__device__ __half g_ath[MTOT];                      // att fp16
__device__ __half g_onh[MTOT], g_onl[MTOT];
__device__ __half g_th[MTOT],  g_tl[MTOT];          // FFN pre-activation pair
__device__ __half g_hh[MTOT],  g_hl[MTOT];          // h1
__device__ __half g_h2h[MTOT], g_h2l[MTOT];         // h2
__device__ __half g_sh[8LL * 2048 * 2048];
__device__ __half g_wth[6 * 512 * 512];             // W^T planes

// ---------------- helpers ----------------
__device__ __forceinline__ uint32_t smem_u32(const void* p) {
    uint32_t a;
    asm("{ .reg .u64 t; cvta.to.shared.u64 t, %1; cvt.u32.u64 %0, t; }"
        : "=r"(a) : "l"(p));
    return a;
}
__device__ __forceinline__ void cpa16(uint32_t dst, const void* src) {
    asm volatile("cp.async.cg.shared.global [%0], [%1], 16;"
                 :: "r"(dst), "l"(src) : "memory");
}
#define CP_COMMIT() asm volatile("cp.async.commit_group;" ::: "memory")
#define CP_WAIT0()  asm volatile("cp.async.wait_group 0;"  ::: "memory")
#define CP_WAIT1()  asm volatile("cp.async.wait_group 1;"  ::: "memory")
#define CP_WAIT2()  asm volatile("cp.async.wait_group 2;"  ::: "memory")

#define MMA_F16(c, a0, a1, a2, a3, b0, b1)                                    \
    asm volatile("mma.sync.aligned.m16n8k16.row.col.f32.f16.f16.f32 "         \
        "{%0,%1,%2,%3}, {%4,%5,%6,%7}, {%8,%9}, {%0,%1,%2,%3};"               \
        : "+f"((c)[0]), "+f"((c)[1]), "+f"((c)[2]), "+f"((c)[3])              \
        : "r"(a0), "r"(a1), "r"(a2), "r"(a3), "r"(b0), "r"(b1))

// fp16 accumulator variant: D/C are 2 regs (4 halves)
#define MMA_H16(c, a0, a1, a2, a3, b0, b1)                                    \
    asm volatile("mma.sync.aligned.m16n8k16.row.col.f16.f16.f16.f16 "         \
        "{%0,%1}, {%2,%3,%4,%5}, {%6,%7}, {%0,%1};"                           \
        : "+r"((c)[0]), "+r"((c)[1])                                          \
        : "r"(a0), "r"(a1), "r"(a2), "r"(a3), "r"(b0), "r"(b1))

__device__ __forceinline__ void ldsm_x4(uint32_t& r0, uint32_t& r1,
                                        uint32_t& r2, uint32_t& r3, uint32_t a) {
    asm volatile("ldmatrix.sync.aligned.m8n8.x4.shared.b16 {%0,%1,%2,%3}, [%4];"
                 : "=r"(r0), "=r"(r1), "=r"(r2), "=r"(r3) : "r"(a));
}

__device__ __forceinline__ void split2(float a, float b, __half2& h, __half2& l) {
    h = __floats2half2_rn(a, b);
    l = __floats2half2_rn(a - __half2float(h.x), b - __half2float(h.y));
}

// ---------------- common tiling constants ----------------
// Block tile 128x128, BK=32, 8 warps (2x4), warp tile 64x32, 256 threads.
#define RSTRIDE 80
#define PLANE_B 10240
#define SMEM_H  (3 * 2 * PLANE_B)   // fp16-acc: 3-stage, 2 planes = 61440
#define SMEM_P1 (4 * 2 * PLANE_B)   // fp32-acc NPROD=1: 4-stage  = 81920
#define SMEM_P2 (3 * 3 * PLANE_B)   // fp32-acc NPROD=2: 3-stage  = 92160

// ===========================================================================
// fp16-accumulator GEMM: C(hi fp16) = alpha * A@B^T + bias. 3 CTA/SM target.
// biasMode: 0 = bias[col], 1 = bias[row], 2 = none.
// ===========================================================================
__global__ __launch_bounds__(256, 3) void mma_gemm_h(
    const __half* __restrict__ Ah, const __half* __restrict__ Bh,
    const float* __restrict__ bias, int biasMode,
    __half* __restrict__ Ch,
    int ldA, int ldB, int ldC, int K, float alpha,
    long long sA, long long sB, long long sC)
{
    constexpr int NSTG = 3;
    constexpr uint32_t STAGE = 2 * PLANE_B;
    constexpr uint32_t BOFF  = PLANE_B;

    extern __shared__ __align__(16) uint32_t sm[];
    const uint32_t sbase = smem_u32(sm);

    const int bz = blockIdx.z;
    Ah += (long long)bz * sA;
    Bh += (long long)bz * sB;

    const int m0 = blockIdx.y * 128;
    const int n0 = blockIdx.x * 128;
    const int tid  = threadIdx.x;
    const int wid  = tid >> 5, lane = tid & 31;
    const int wm   = wid >> 2, wn = wid & 3;
    const int g    = lane >> 2, t = lane & 3;

    const int lrow = tid >> 1;
    const int lseg = (tid & 1) * 2;
    const char* gAh = (const char*)(Ah + (long long)(m0 + lrow) * ldA) + lseg * 16;
    const char* gBh = (const char*)(Bh + (long long)(n0 + lrow) * ldB) + lseg * 16;
    const uint32_t dst0 = sbase + lrow * RSTRIDE + lseg * 16;

    const uint32_t a_off = (uint32_t)(wm * 64 + (lane & 15)) * RSTRIDE
                         + (uint32_t)(lane >> 4) * 16u;
    const uint32_t b_off = (uint32_t)(wn * 32 + (lane & 7) + ((lane >> 4) & 1) * 8) * RSTRIDE
                         + (uint32_t)((lane >> 3) & 1) * 16u;

    uint32_t acc[4][4][2];
#pragma unroll
    for (int i = 0; i < 4; i++)
#pragma unroll
        for (int j = 0; j < 4; j++) { acc[i][j][0] = 0u; acc[i][j][1] = 0u; }

    const int NCH = K >> 5;

    auto PREF = [&](int chv) {
        const uint32_t so = (uint32_t)(chv % NSTG) * STAGE;
        const long long go = (long long)chv * 64;
        cpa16(dst0 + so,             gAh + go);
        cpa16(dst0 + so + 16,        gAh + go + 16);
        cpa16(dst0 + so + BOFF,      gBh + go);
        cpa16(dst0 + so + BOFF + 16, gBh + go + 16);
    };

    {
        const int npre = (NCH < 2) ? NCH : 2;
        for (int i = 0; i < npre; i++) { PREF(i); CP_COMMIT(); }
    }
    for (int ch = 0; ch < NCH; ch++) {
        const int rem = NCH - 1 - ch;
        if (rem <= 0)      CP_WAIT0();
        else               CP_WAIT1();
        __syncthreads();
        if (ch + 2 < NCH) { PREF(ch + 2); CP_COMMIT(); }

        const uint32_t sb = sbase + (uint32_t)(ch % NSTG) * STAGE;
        const uint32_t aA = sb + a_off;
        const uint32_t aB = sb + BOFF + b_off;
#pragma unroll
        for (int ks = 0; ks < 2; ks++) {
            const uint32_t ko = ks * 32;
            uint32_t bh[4][2];
            ldsm_x4(bh[0][0], bh[0][1], bh[1][0], bh[1][1], aB + ko);
            ldsm_x4(bh[2][0], bh[2][1], bh[3][0], bh[3][1], aB + 16 * RSTRIDE + ko);
#pragma unroll
            for (int mi = 0; mi < 4; mi++) {
                uint32_t ah[4];
                ldsm_x4(ah[0], ah[1], ah[2], ah[3], aA + mi * 16 * RSTRIDE + ko);
#pragma unroll
                for (int ni = 0; ni < 4; ni++)
                    MMA_H16(acc[mi][ni], ah[0], ah[1], ah[2], ah[3],
                            bh[ni][0], bh[ni][1]);
            }
        }
    }

    // epilogue (fp16 math)
    __half* ChB = Ch + (long long)bz * sC;
    const __half2 alph = __half2half2(__float2half(alpha));
#pragma unroll
    for (int mi = 0; mi < 4; mi++) {
#pragma unroll
        for (int ni = 0; ni < 4; ni++) {
            const int r0 = m0 + wm * 64 + mi * 16 + g;
            const int c  = n0 + wn * 32 + ni * 8 + t * 2;
            __half2 v0 = __hmul2(*(__half2*)&acc[mi][ni][0], alph);
            __half2 v1 = __hmul2(*(__half2*)&acc[mi][ni][1], alph);
            if (biasMode == 0) {
                const __half2 bb = __floats2half2_rn(bias[c], bias[c + 1]);
                v0 = __hadd2(v0, bb);
                v1 = __hadd2(v1, bb);
            } else if (biasMode == 1) {
                v0 = __hadd2(v0, __float2half2_rn(bias[r0]));
                v1 = __hadd2(v1, __float2half2_rn(bias[r0 + 8]));
            }
            ((__half2*)ChB)[((long long)r0 * ldC + c) >> 1]       = v0;
            ((__half2*)ChB)[((long long)(r0 + 8) * ldC + c) >> 1] = v1;
        }
    }
}

// ===========================================================================
// fp32-accumulator GEMM (att + FFN). NPROD=1: [A,B] 4-stage; NPROD=2: +Al.
// OUTM: 0 = fp32; 1 = fp16 pair; 2 = fp16 hi.  biasMode: 0=col.
// ===========================================================================
template <int NPROD, int OUTM>
__global__ __launch_bounds__(256, 2) void mma_gemm(
    const __half* __restrict__ Ah, const __half* __restrict__ Al,
    const __half* __restrict__ Bh,
    const float* __restrict__ bias,
    float* __restrict__ Cf, __half* __restrict__ Ch, __half* __restrict__ Cl,
    int ldA, int ldB, int ldC, int K, float alpha,
    long long sA, long long sB, long long sC)
{
    constexpr int NSTG = (NPROD == 1) ? 4 : 3;
    constexpr uint32_t STAGE = (NPROD == 1) ? 2 * PLANE_B : 3 * PLANE_B;
    constexpr uint32_t BOFF  = (NPROD == 1) ? PLANE_B : 2 * PLANE_B;

    extern __shared__ __align__(16) uint32_t sm[];
    const uint32_t sbase = smem_u32(sm);

    const int bz = blockIdx.z;
    Ah += (long long)bz * sA;
    if (NPROD >= 2) Al += (long long)bz * sA;
    Bh += (long long)bz * sB;

    const int m0 = blockIdx.y * 128;
    const int n0 = blockIdx.x * 128;
    const int tid  = threadIdx.x;
    const int wid  = tid >> 5, lane = tid & 31;
    const int wm   = wid >> 2, wn = wid & 3;
    const int g    = lane >> 2, t = lane & 3;

    const int lrow = tid >> 1;
    const int lseg = (tid & 1) * 2;
    const char* gAh = (const char*)(Ah + (long long)(m0 + lrow) * ldA) + lseg * 16;
    const char* gAl = (NPROD >= 2)
        ? (const char*)(Al + (long long)(m0 + lrow) * ldA) + lseg * 16 : nullptr;
    const char* gBh = (const char*)(Bh + (long long)(n0 + lrow) * ldB) + lseg * 16;
    const uint32_t dst0 = sbase + lrow * RSTRIDE + lseg * 16;

    const uint32_t a_off = (uint32_t)(wm * 64 + (lane & 15)) * RSTRIDE
                         + (uint32_t)(lane >> 4) * 16u;
    const uint32_t b_off = (uint32_t)(wn * 32 + (lane & 7) + ((lane >> 4) & 1) * 8) * RSTRIDE
                         + (uint32_t)((lane >> 3) & 1) * 16u;

    float acc[4][4][4];
#pragma unroll
    for (int i = 0; i < 4; i++)
#pragma unroll
        for (int j = 0; j < 4; j++)
#pragma unroll
            for (int e = 0; e < 4; e++) acc[i][j][e] = 0.0f;

    const int NCH = K >> 5;

    auto PREF = [&](int chv) {
        const uint32_t so = (uint32_t)(chv % NSTG) * STAGE;
        const long long go = (long long)chv * 64;
        cpa16(dst0 + so,      gAh + go);
        cpa16(dst0 + so + 16, gAh + go + 16);
        if (NPROD >= 2) {
            cpa16(dst0 + so + PLANE_B,      gAl + go);
            cpa16(dst0 + so + PLANE_B + 16, gAl + go + 16);
        }
        cpa16(dst0 + so + BOFF,      gBh + go);
        cpa16(dst0 + so + BOFF + 16, gBh + go + 16);
    };

    auto COMPUTE = [&](int ch) {
        const uint32_t sb = sbase + (uint32_t)(ch % NSTG) * STAGE;
        const uint32_t aA  = sb + a_off;
        const uint32_t aAl = sb + PLANE_B + a_off;
        const uint32_t aB  = sb + BOFF + b_off;
#pragma unroll
        for (int ks = 0; ks < 2; ks++) {
            const uint32_t ko = ks * 32;
            uint32_t bh[4][2];
            ldsm_x4(bh[0][0], bh[0][1], bh[1][0], bh[1][1], aB + ko);
            ldsm_x4(bh[2][0], bh[2][1], bh[3][0], bh[3][1], aB + 16 * RSTRIDE + ko);
#pragma unroll
            for (int mi = 0; mi < 4; mi++) {
                uint32_t ah[4];
                ldsm_x4(ah[0], ah[1], ah[2], ah[3], aA + mi * 16 * RSTRIDE + ko);
#pragma unroll
                for (int ni = 0; ni < 4; ni++)
                    MMA_F16(acc[mi][ni], ah[0], ah[1], ah[2], ah[3], bh[ni][0], bh[ni][1]);
                if (NPROD >= 2) {
                    uint32_t al[4];
                    ldsm_x4(al[0], al[1], al[2], al[3], aAl + mi * 16 * RSTRIDE + ko);
#pragma unroll
                    for (int ni = 0; ni < 4; ni++)
                        MMA_F16(acc[mi][ni], al[0], al[1], al[2], al[3], bh[ni][0], bh[ni][1]);
                }
            }
        }
    };

    {
        const int npre = (NCH < NSTG - 1) ? NCH : (NSTG - 1);
        for (int i = 0; i < npre; i++) { PREF(i); CP_COMMIT(); }
    }
    for (int ch = 0; ch < NCH; ch++) {
        int w = NSTG - 2;
        const int rem = NCH - 1 - ch;
        if (rem < w) w = rem;
        if (w <= 0)      CP_WAIT0();
        else if (w == 1) CP_WAIT1();
        else             CP_WAIT2();
        __syncthreads();
        if (ch + NSTG - 1 < NCH) { PREF(ch + NSTG - 1); CP_COMMIT(); }
        COMPUTE(ch);
    }

    float*  CfB = Cf + (long long)bz * sC;
    __half* ChB = Ch + (long long)bz * sC;
    __half* ClB = Cl + (long long)bz * sC;

#pragma unroll
    for (int mi = 0; mi < 4; mi++) {
#pragma unroll
        for (int ni = 0; ni < 4; ni++) {
            const int r0 = m0 + wm * 64 + mi * 16 + g;
            const int c  = n0 + wn * 32 + ni * 8 + t * 2;
            float v0 = acc[mi][ni][0] * alpha, v1 = acc[mi][ni][1] * alpha;
            float v2 = acc[mi][ni][2] * alpha, v3 = acc[mi][ni][3] * alpha;
            if (bias) {
                const float b0 = bias[c], b1 = bias[c + 1];
                v0 += b0; v1 += b1; v2 += b0; v3 += b1;
            }
            if (OUTM == 0) {
                *(float2*)&CfB[(long long)r0 * ldC + c]       = make_float2(v0, v1);
                *(float2*)&CfB[(long long)(r0 + 8) * ldC + c] = make_float2(v2, v3);
            } else if (OUTM == 1) {
                __half2 h0, l0, h1, l1;
                split2(v0, v1, h0, l0);
                split2(v2, v3, h1, l1);
                ((__half2*)ChB)[((long long)r0 * ldC + c) >> 1]       = h0;
                ((__half2*)ClB)[((long long)r0 * ldC + c) >> 1]       = l0;
                ((__half2*)ChB)[((long long)(r0 + 8) * ldC + c) >> 1] = h1;
                ((__half2*)ClB)[((long long)(r0 + 8) * ldC + c) >> 1] = l1;
            } else {
                ((__half2*)ChB)[((long long)r0 * ldC + c) >> 1]       = __floats2half2_rn(v0, v1);
                ((__half2*)ChB)[((long long)(r0 + 8) * ldC + c) >> 1] = __floats2half2_rn(v2, v3);
            }
        }
    }
}

// ---------------- fp32 -> fp16 ----------------
__global__ __launch_bounds__(256) void tohalf_kernel(
    const float* __restrict__ in, __half* __restrict__ oh, int n4)
{
    const int i = blockIdx.x * 256 + threadIdx.x;
    if (i >= n4) return;
    float4 v = ((const float4*)in)[i];
    ((__half2*)oh)[i * 2]     = __floats2half2_rn(v.x, v.y);
    ((__half2*)oh)[i * 2 + 1] = __floats2half2_rn(v.z, v.w);
}

// ------------- transpose: fp32 [R][C] -> fp16 [C][R] ----------
__global__ __launch_bounds__(256) void tsplit_kernel(
    const float* __restrict__ in, __half* __restrict__ oh,
    int R, int C, long long sI, long long sO)
{
    __shared__ float tile[32][33];
    const int z = blockIdx.z;
    in += (long long)z * sI;
    oh += (long long)z * sO;
    const int c0 = blockIdx.x * 32, r0 = blockIdx.y * 32;
    const int tx = threadIdx.x & 31, ty = threadIdx.x >> 5;

#pragma unroll
    for (int i = 0; i < 4; i++)
        tile[ty + i * 8][tx] = in[(long long)(r0 + ty + i * 8) * C + c0 + tx];
    __syncthreads();
#pragma unroll
    for (int i = 0; i < 4; i++) {
        const float v = tile[tx][ty + i * 8];
        oh[(long long)(c0 + ty + i * 8) * R + r0 + tx] = __float2half_rn(v);
    }
}

// -------- softmax, in-place on fp16 plane (row = 2048) --------
__device__ __forceinline__ float warpMax(float v) {
#pragma unroll
    for (int o = 16; o > 0; o >>= 1) v = fmaxf(v, __shfl_xor_sync(0xffffffffu, v, o));
    return v;
}
__device__ __forceinline__ float warpSum(float v) {
#pragma unroll
    for (int o = 16; o > 0; o >>= 1) v += __shfl_xor_sync(0xffffffffu, v, o);
    return v;
}

__global__ __launch_bounds__(256) void softmax_kernel(__half* __restrict__ H)
{
    const long long base = (long long)blockIdx.x * 2048;
    __half2* rh = (__half2*)(H + base);
    const int tid = threadIdx.x;
    const int lane = tid & 31, wid = tid >> 5;
    __shared__ float sh[8];

    float v[8];
#pragma unroll
    for (int j = 0; j < 4; j++) {
        const __half2 hv = rh[tid * 4 + j];
        v[2*j]   = __half2float(hv.x);
        v[2*j+1] = __half2float(hv.y);
    }

    float m = v[0];
#pragma unroll
    for (int i = 1; i < 8; i++) m = fmaxf(m, v[i]);
    m = warpMax(m);
    if (lane == 0) sh[wid] = m;
    __syncthreads();
    m = sh[0];
#pragma unroll
    for (int w = 1; w < 8; w++) m = fmaxf(m, sh[w]);

    float e[8];
    float s = 0.0f;
#pragma unroll
    for (int i = 0; i < 8; i++) { e[i] = __expf(v[i] - m); s += e[i]; }
    s = warpSum(s);
    __syncthreads();
    if (lane == 0) sh[wid] = s;
    __syncthreads();
    float tot = 0.0f;
#pragma unroll
    for (int w = 0; w < 8; w++) tot += sh[w];
    const float inv = 1.0f / tot;

#pragma unroll
    for (int j = 0; j < 4; j++)
        rh[tid * 4 + j] = __floats2half2_rn(e[2*j] * inv, e[2*j+1] * inv);
}

// ---------------- fused add(+gelu)+LN, fp16-pair I/O ----------------
template <int MODE, bool XPAIR, bool YPAIR>
__global__ __launch_bounds__(128) void rowln_kernel(
    const float* __restrict__ Xf,
    const __half* __restrict__ Xh, const __half* __restrict__ Xl,
    const __half* __restrict__ Yh, const __half* __restrict__ Yl,
    const float* __restrict__ g, const float* __restrict__ b,
    __half* __restrict__ Oh, __half* __restrict__ Ol)
{
    const long long row = (long long)blockIdx.x * 512;
    const int tid = threadIdx.x;
    const int lane = tid & 31, wid = tid >> 5;
    __shared__ float s1[4], s2[4];

    float t[4];
    float sum = 0.0f, sq = 0.0f;
#pragma unroll
    for (int i = 0; i < 4; i++) {
        const int c = tid + i * 128;
        float xv;
        if (XPAIR) xv = __half2float(Xh[row + c]) + __half2float(Xl[row + c]);
        else       xv = Xf[row + c];
        float yv = __half2float(Yh[row + c]);
        if (YPAIR)  yv += __half2float(Yl[row + c]);
        float u = xv + yv;
        if (MODE == 1) u = 0.5f * u * (1.0f + erff(u * 0.7071067811865476f));
        t[i] = u;
        sum += u;
        sq += u * u;
    }
    sum = warpSum(sum);
    sq = warpSum(sq);
    if (lane == 0) { s1[wid] = sum; s2[wid] = sq; }
    __syncthreads();
    float ts = 0.0f, tq = 0.0f;
#pragma unroll
    for (int w = 0; w < 4; w++) { ts += s1[w]; tq += s2[w]; }
    const float mean = ts * (1.0f / 512.0f);
    const float var = tq * (1.0f / 512.0f) - mean * mean;
    const float inv = rsqrtf(var + 1e-5f);

#pragma unroll
    for (int i = 0; i < 4; i++) {
        const int c = tid + i * 128;
        const float o = (t[i] - mean) * inv * g[c] + b[c];
        const __half h = __float2half_rn(o);
        Oh[row + c] = h;
        Ol[row + c] = __float2half_rn(o - __half2float(h));
    }
}

// ---------------- host ----------------
template <typename T>
static T* symaddr(const void* sym)
{
    void* p = nullptr;
    cudaGetSymbolAddress(&p, sym);
    return (T*)p;
}

extern "C" void kernel_launch(void* const* d_in, const int* in_sizes, int n_in,
                              void* d_out, int out_size)
{
    const float* x    = (const float*)d_in[0];
    const float* Wq   = (const float*)d_in[1];
    const float* bq   = (const float*)d_in[2];
    const float* Wk   = (const float*)d_in[3];
    const float* bk   = (const float*)d_in[4];
    const float* Wv   = (const float*)d_in[5];
    const float* bv   = (const float*)d_in[6];
    const float* ln0g = (const float*)d_in[7];
    const float* ln0b = (const float*)d_in[8];
    const float* W1   = (const float*)d_in[9];
    const float* b1   = (const float*)d_in[10];
    const float* ln1g = (const float*)d_in[11];
    const float* ln1b = (const float*)d_in[12];
    const float* W2   = (const float*)d_in[13];
    const float* b2   = (const float*)d_in[14];
    const float* ln2g = (const float*)d_in[15];
    const float* ln2b = (const float*)d_in[16];
    const float* W3   = (const float*)d_in[17];
    const float* b3   = (const float*)d_in[18];
    float* out = (float*)d_out;

    __half* xh  = symaddr<__half>(g_xh);
    __half* qh  = symaddr<__half>(g_qh);
    __half* kh  = symaddr<__half>(g_kh);
    __half* vth = symaddr<__half>(g_vth);
    __half* ath = symaddr<__half>(g_ath);
    __half* onh = symaddr<__half>(g_onh);  __half* onl = symaddr<__half>(g_onl);
    __half* th  = symaddr<__half>(g_th);   __half* tl  = symaddr<__half>(g_tl);
    __half* hh  = symaddr<__half>(g_hh);   __half* hl  = symaddr<__half>(g_hl);
    __half* h2h = symaddr<__half>(g_h2h);  __half* h2l = symaddr<__half>(g_h2l);
    __half* sh_ = symaddr<__half>(g_sh);
    __half* wth = symaddr<__half>(g_wth);

    cudaFuncSetAttribute(mma_gemm_h,    cudaFuncAttributeMaxDynamicSharedMemorySize, SMEM_H);
    cudaFuncSetAttribute(mma_gemm<1,2>, cudaFuncAttributeMaxDynamicSharedMemorySize, SMEM_P1);
    cudaFuncSetAttribute(mma_gemm<2,0>, cudaFuncAttributeMaxDynamicSharedMemorySize, SMEM_P2);
    cudaFuncSetAttribute(mma_gemm<2,1>, cudaFuncAttributeMaxDynamicSharedMemorySize, SMEM_P2);

    const long long sSD = 2048LL * 512;
    const long long sSS = 2048LL * 2048;
    const long long WSZ = 512LL * 512;
    const float scale = 0.044194173824159216f;   // 1/sqrt(512)

    dim3 gW(16, 16, 1);
    dim3 bT(256);
    dim3 gProj(4, 128, 1);     // N=512, M=16384
    dim3 gScores(16, 16, 8);   // per batch 2048x2048
    dim3 gVt(128, 4, 1);       // N=16384, M=512
    dim3 gAtt(4, 16, 8);

    // 1-3: q/k inputs
    tohalf_kernel<<<MTOT / 1024, 256>>>(x, xh, MTOT / 4);
    tsplit_kernel<<<gW, bT>>>(Wq, wth + 0 * WSZ, 512, 512, 0, 0);
    tsplit_kernel<<<gW, bT>>>(Wk, wth + 1 * WSZ, 512, 512, 0, 0);

    // 4-5: q, k (fp16 acc, 3 CTA/SM)
    mma_gemm_h<<<gProj, 256, SMEM_H>>>(xh, wth + 0 * WSZ,
        bq, 0, qh, 512, 512, 512, 512, 1.0f, 0, 0, 0);
    mma_gemm_h<<<gProj, 256, SMEM_H>>>(xh, wth + 1 * WSZ,
        bk, 0, kh, 512, 512, 512, 512, 1.0f, 0, 0, 0);

    // 6: scores = q @ k^T * scale (fp16 acc; ncu profiles this launch)
    mma_gemm_h<<<gScores, 256, SMEM_H>>>(qh, kh,
        nullptr, 2, sh_, 512, 512, 2048, 512, scale, sSD, sSD, sSS);

    // 7: softmax in-place
    softmax_kernel<<<16384, 256>>>(sh_);

    // 8-9: v^T = Wv^T @ x^T (row bias bv), fp16 acc -> [512][16384]
    tsplit_kernel<<<gW, bT>>>(Wv, wth + 2 * WSZ, 512, 512, 0, 0);
    mma_gemm_h<<<gVt, 256, SMEM_H>>>(wth + 2 * WSZ, xh,
        bv, 1, vth, 512, 512, 16384, 512, 1.0f, 0, 0, 0);

    // 10: att = w @ v (fp32 acc) -> fp16 hi
    mma_gemm<1,2><<<gAtt, 256, SMEM_P1>>>(sh_, nullptr, vth,
        nullptr, nullptr, ath, nullptr, 2048, 16384, 512, 2048, 1.0f,
        sSS, 2048, sSD);

    // 11: out_nxt = LN(x + att) -> pair
    rowln_kernel<0, false, false><<<16384, 128>>>(
        x, nullptr, nullptr, ath, nullptr, ln0g, ln0b, onh, onl);

    // 12-14: h1 = LN(gelu(on + on@W1 + b1))
    tsplit_kernel<<<gW, bT>>>(W1, wth + 3 * WSZ, 512, 512, 0, 0);
    mma_gemm<2,1><<<gProj, 256, SMEM_P2>>>(onh, onl, wth + 3 * WSZ,
        b1, nullptr, th, tl, 512, 512, 512, 512, 1.0f, 0, 0, 0);
    rowln_kernel<1, true, true><<<16384, 128>>>(
        nullptr, onh, onl, th, tl, ln1g, ln1b, hh, hl);

    // 15-17: h2 = LN(gelu(on + h1@W2 + b2))
    tsplit_kernel<<<gW, bT>>>(W2, wth + 4 * WSZ, 512, 512, 0, 0);
    mma_gemm<2,1><<<gProj, 256, SMEM_P2>>>(hh, hl, wth + 4 * WSZ,
        b2, nullptr, th, tl, 512, 512, 512, 512, 1.0f, 0, 0, 0);
    rowln_kernel<1, true, true><<<16384, 128>>>(
        nullptr, onh, onl, th, tl, ln2g, ln2b, h2h, h2l);

    // 18-19: out = h2 @ W3 + b3 (fp32)
    tsplit_kernel<<<gW, bT>>>(W3, wth + 5 * WSZ, 512, 512, 0, 0);
    mma_gemm<2,0><<<gProj, 256, SMEM_P2>>>(h2h, h2l, wth + 5 * WSZ,
        b3, out, nullptr, nullptr, 512, 512, 512, 512, 1.0f, 0, 0, 0);
}